// round 5
// baseline (speedup 1.0000x reference)
#include <cuda_runtime.h>
#include <math.h>

// ---------------- problem constants ----------------
#define BATCH   8
#define CH      96
#define NTOK    3136          // 56*56
#define COUT    192
#define NPOS    (BATCH * NTOK)   // 25088

// attention tiling
#define MQ      112           // query rows per block (3136 = 28*112)
#define NKEY    64            // keys per tile
#define NTILES  49            // 3136/64
#define QS_STRIDE 100
#define KS_STRIDE 100
#define PS_STRIDE 68

// smem sizes (floats)
#define QS_OFF  0
#define KS_OFF  (MQ * QS_STRIDE)                 // 11200
#define PS_OFF  (KS_OFF + NKEY * KS_STRIDE)      // 17600
#define ST_OFF  (PS_OFF + MQ * PS_STRIDE)        // 25216
#define ATTN_SMEM_FLOATS (ST_OFF + 3 * MQ + 16)
#define ATTN_SMEM_BYTES  (ATTN_SMEM_FLOATS * 4)

// conv kernel smem
#define WS_STRIDE 193
#define CS_STRIDE 33
#define CONV_SMEM_FLOATS (COUT * WS_STRIDE + (2*CH) * CS_STRIDE)
#define CONV_SMEM_BYTES  (CONV_SMEM_FLOATS * 4)
#define CONV_POS 32
#define NCONVBLK (NPOS / CONV_POS)   // 784

// ---------------- scratch (no allocation allowed) ----------------
__device__ float g_xj[BATCH * CH * NTOK];       // relu(x - att), [b,c,n] layout
__device__ float g_y [COUT * NPOS];             // conv output, [o, b*N+n]
__device__ float g_p1[NCONVBLK * COUT];         // partial sum(y)
__device__ float g_p2[NCONVBLK * COUT];         // partial sum(y^2)
__device__ float g_scale[COUT];
__device__ float g_shift[COUT];

// =====================================================================
// Kernel 1: flash attention (q=k=v=x tokens) + x_j = relu(x - att)
// grid (28, 8), 128 threads, 2 blocks/SM -> single wave (224 blocks)
// thread grid: ty = tid/8 (0..15), tx = tid%8 (0..7)
// S micro-tile 7x8  (rows i = ii*16+ty, cols j = jj*8+tx)
// O micro-tile 7x12 (rows i = ii*16+ty, cols ch = jj*8+tx)
// =====================================================================
__global__ void __launch_bounds__(128, 2)
attn_kernel(const float* __restrict__ x)
{
    extern __shared__ float sm[];
    float* Qs   = sm + QS_OFF;
    float* Ks   = sm + KS_OFF;
    float* Ps   = sm + PS_OFF;
    float* mrow = sm + ST_OFF;
    float* lrow = mrow + MQ;
    float* arow = lrow + MQ;

    const int tid = threadIdx.x;
    const int ty  = tid >> 3;        // 0..15
    const int tx  = tid & 7;         // 0..7
    const int b   = blockIdx.y;
    const int n0  = blockIdx.x * MQ;
    const float* xb = x + (size_t)b * CH * NTOK;

    // load Q tile 112 x 96 (vectorized over n)
    for (int v = tid; v < (MQ * CH) / 4; v += 128) {
        int c  = v / (MQ / 4);
        int r4 = (v - c * (MQ / 4)) * 4;
        float4 t = *(const float4*)(xb + c * NTOK + n0 + r4);
        Qs[(r4 + 0) * QS_STRIDE + c] = t.x;
        Qs[(r4 + 1) * QS_STRIDE + c] = t.y;
        Qs[(r4 + 2) * QS_STRIDE + c] = t.z;
        Qs[(r4 + 3) * QS_STRIDE + c] = t.w;
    }
    if (tid < MQ) { mrow[tid] = -INFINITY; lrow[tid] = 0.f; }

    float o_acc[7][12];
    #pragma unroll
    for (int i = 0; i < 7; i++)
        #pragma unroll
        for (int j = 0; j < 12; j++) o_acc[i][j] = 0.f;

    __syncthreads();

    for (int t = 0; t < NTILES; t++) {
        // ---- load K tile 64 x 96 ----
        for (int v = tid; v < (NKEY * CH) / 4; v += 128) {
            int c  = v / (NKEY / 4);
            int r4 = (v - c * (NKEY / 4)) * 4;
            float4 tv = *(const float4*)(xb + c * NTOK + t * NKEY + r4);
            Ks[(r4 + 0) * KS_STRIDE + c] = tv.x;
            Ks[(r4 + 1) * KS_STRIDE + c] = tv.y;
            Ks[(r4 + 2) * KS_STRIDE + c] = tv.z;
            Ks[(r4 + 3) * KS_STRIDE + c] = tv.w;
        }
        __syncthreads();

        // ---- S = Q K^T  (112 x 64), micro 7x8 ----
        float s_acc[7][8];
        #pragma unroll
        for (int i = 0; i < 7; i++)
            #pragma unroll
            for (int j = 0; j < 8; j++) s_acc[i][j] = 0.f;

        for (int c = 0; c < CH; c += 4) {
            float4 aa[7], bb[8];
            #pragma unroll
            for (int ii = 0; ii < 7; ii++)
                aa[ii] = *(const float4*)&Qs[(ii * 16 + ty) * QS_STRIDE + c];
            #pragma unroll
            for (int jj = 0; jj < 8; jj++)
                bb[jj] = *(const float4*)&Ks[(jj * 8 + tx) * KS_STRIDE + c];
            #pragma unroll
            for (int ii = 0; ii < 7; ii++) {
                #pragma unroll
                for (int jj = 0; jj < 8; jj++) {
                    s_acc[ii][jj] += aa[ii].x * bb[jj].x;
                    s_acc[ii][jj] += aa[ii].y * bb[jj].y;
                    s_acc[ii][jj] += aa[ii].z * bb[jj].z;
                    s_acc[ii][jj] += aa[ii].w * bb[jj].w;
                }
            }
        }
        #pragma unroll
        for (int ii = 0; ii < 7; ii++)
            #pragma unroll
            for (int jj = 0; jj < 8; jj++)
                Ps[(ii * 16 + ty) * PS_STRIDE + jj * 8 + tx] = s_acc[ii][jj];
        __syncthreads();

        // ---- online softmax, one thread per row ----
        if (tid < MQ) {
            const int r = tid;
            float mo = mrow[r];
            float tm = mo;
            #pragma unroll 8
            for (int j = 0; j < NKEY; j++) tm = fmaxf(tm, Ps[r * PS_STRIDE + j]);
            float al = __expf(mo - tm);
            float sum = 0.f;
            #pragma unroll 8
            for (int j = 0; j < NKEY; j++) {
                float p = __expf(Ps[r * PS_STRIDE + j] - tm);
                Ps[r * PS_STRIDE + j] = p;
                sum += p;
            }
            lrow[r] = lrow[r] * al + sum;
            mrow[r] = tm;
            arow[r] = al;
        }
        __syncthreads();

        // ---- rescale O, then O += P * V (V = K tile) ----
        float alpha_i[7];
        #pragma unroll
        for (int ii = 0; ii < 7; ii++) alpha_i[ii] = arow[ii * 16 + ty];
        #pragma unroll
        for (int ii = 0; ii < 7; ii++)
            #pragma unroll
            for (int jj = 0; jj < 12; jj++) o_acc[ii][jj] *= alpha_i[ii];

        for (int kk = 0; kk < NKEY; kk += 4) {
            float4 av[7];
            #pragma unroll
            for (int ii = 0; ii < 7; ii++)
                av[ii] = *(const float4*)&Ps[(ii * 16 + ty) * PS_STRIDE + kk];
            #pragma unroll
            for (int dk = 0; dk < 4; dk++) {
                float bb[12];
                #pragma unroll
                for (int jj = 0; jj < 12; jj++)
                    bb[jj] = Ks[(kk + dk) * KS_STRIDE + jj * 8 + tx];
                #pragma unroll
                for (int ii = 0; ii < 7; ii++) {
                    float a = (&av[ii].x)[dk];
                    #pragma unroll
                    for (int jj = 0; jj < 12; jj++)
                        o_acc[ii][jj] += a * bb[jj];
                }
            }
        }
        __syncthreads();
    }

    // ---- epilogue: x_j = relu(x - att) ----
    float inv[7];
    #pragma unroll
    for (int ii = 0; ii < 7; ii++) inv[ii] = 1.f / lrow[ii * 16 + ty];
    #pragma unroll
    for (int ii = 0; ii < 7; ii++) {
        const int n = n0 + ii * 16 + ty;
        #pragma unroll
        for (int jj = 0; jj < 12; jj++) {
            const int ch = jj * 8 + tx;
            float xv  = xb[ch * NTOK + n];
            float att = o_acc[ii][jj] * inv[ii];
            g_xj[((size_t)b * CH + ch) * NTOK + n] = fmaxf(xv - att, 0.f);
        }
    }
}

// =====================================================================
// Kernel 2: 1x1 conv y = W [x; x_j] + bias, + per-block channel partial sums
// grid 784, 256 threads. W fully in smem.
// to = tid/8 owns 6 output channels {to*6..}, tp = tid%8 owns 4 positions.
// =====================================================================
__global__ void __launch_bounds__(256, 1)
conv_kernel(const float* __restrict__ x, const float* __restrict__ w,
            const float* __restrict__ bias)
{
    extern __shared__ float sm[];
    float* Ws = sm;                       // 192 x 193
    float* cs = sm + COUT * WS_STRIDE;    // 192 x 33

    const int tid = threadIdx.x;
    for (int i = tid; i < COUT * (2 * CH); i += 256) {
        int o = i / (2 * CH), k = i - o * (2 * CH);
        Ws[o * WS_STRIDE + k] = w[i];
    }

    const int p0 = blockIdx.x * CONV_POS;
    const int b  = p0 / NTOK;
    const int n0 = p0 - b * NTOK;

    for (int i = tid; i < CH * CONV_POS; i += 256) {
        int k = i / CONV_POS, pp = i - k * CONV_POS;
        size_t gi = ((size_t)b * CH + k) * NTOK + n0 + pp;
        cs[k * CS_STRIDE + pp]          = x[gi];
        cs[(k + CH) * CS_STRIDE + pp]   = g_xj[gi];
    }
    __syncthreads();

    const int to = tid >> 3;   // 0..31
    const int tp = tid & 7;    // 0..7

    float acc[6][4];
    #pragma unroll
    for (int j = 0; j < 6; j++)
        #pragma unroll
        for (int q = 0; q < 4; q++) acc[j][q] = 0.f;

    for (int k = 0; k < 2 * CH; k++) {
        float bb[4];
        #pragma unroll
        for (int q = 0; q < 4; q++) bb[q] = cs[k * CS_STRIDE + tp * 4 + q];
        #pragma unroll
        for (int j = 0; j < 6; j++) {
            float a = Ws[(to * 6 + j) * WS_STRIDE + k];
            #pragma unroll
            for (int q = 0; q < 4; q++) acc[j][q] += a * bb[q];
        }
    }

    #pragma unroll
    for (int j = 0; j < 6; j++) {
        const int o = to * 6 + j;
        const float bi = bias[o];
        float a1 = 0.f, a2 = 0.f;
        #pragma unroll
        for (int q = 0; q < 4; q++) {
            float y = acc[j][q] + bi;
            g_y[(size_t)o * NPOS + p0 + tp * 4 + q] = y;
            a1 += y;
            a2 += y * y;
        }
        // reduce over the 8 position-threads (contiguous lanes, width 8)
        #pragma unroll
        for (int d = 4; d > 0; d >>= 1) {
            a1 += __shfl_down_sync(0xffffffffu, a1, d, 8);
            a2 += __shfl_down_sync(0xffffffffu, a2, d, 8);
        }
        if (tp == 0) {
            g_p1[blockIdx.x * COUT + o] = a1;
            g_p2[blockIdx.x * COUT + o] = a2;
        }
    }
}

// =====================================================================
// Kernel 2b: reduce partials -> per-channel scale/shift (fold BN + gamma/beta)
// grid 192, 256 threads (deterministic reduction, no atomics)
// =====================================================================
__global__ void __launch_bounds__(256)
stats_kernel(const float* __restrict__ gamma, const float* __restrict__ beta)
{
    const int o = blockIdx.x;
    const int tid = threadIdx.x;
    float s1 = 0.f, s2 = 0.f;
    for (int i = tid; i < NCONVBLK; i += 256) {
        s1 += g_p1[i * COUT + o];
        s2 += g_p2[i * COUT + o];
    }
    __shared__ float r1[256], r2[256];
    r1[tid] = s1; r2[tid] = s2;
    __syncthreads();
    for (int d = 128; d > 0; d >>= 1) {
        if (tid < d) { r1[tid] += r1[tid + d]; r2[tid] += r2[tid + d]; }
        __syncthreads();
    }
    if (tid == 0) {
        const float invN = 1.f / (float)NPOS;
        float mean = r1[0] * invN;
        float var  = r2[0] * invN - mean * mean;
        float rstd = rsqrtf(var + 1e-5f);
        float g = gamma[o] * rstd;
        g_scale[o] = g;
        g_shift[o] = beta[o] - mean * g;
    }
}

// =====================================================================
// Kernel 3: BN apply + exact GELU, layout [o, p] -> out [b, o, n]
// total 4816896 elems, float4 per thread, grid 4704 x 256
// =====================================================================
__global__ void __launch_bounds__(256)
bngelu_kernel(float* __restrict__ out)
{
    const int idx4 = blockIdx.x * 256 + threadIdx.x;
    const int base = idx4 * 4;
    const int o = base / NPOS;
    const int p = base - o * NPOS;
    const int b = p / NTOK;
    const int n = p - b * NTOK;

    float4 v = *(const float4*)(g_y + base);
    const float sc = g_scale[o], sh = g_shift[o];
    float r[4] = {v.x, v.y, v.z, v.w};
    #pragma unroll
    for (int i = 0; i < 4; i++) {
        float u = r[i] * sc + sh;
        r[i] = 0.5f * u * (1.f + erff(u * 0.70710678118654752f));
    }
    float4 ov = {r[0], r[1], r[2], r[3]};
    *(float4*)(out + (size_t)b * (COUT * NTOK) + (size_t)o * NTOK + n) = ov;
}

// =====================================================================
extern "C" void kernel_launch(void* const* d_in, const int* in_sizes, int n_in,
                              void* d_out, int out_size)
{
    const float* x     = (const float*)d_in[0];
    const float* w     = (const float*)d_in[1];
    const float* bias  = (const float*)d_in[2];
    const float* gamma = (const float*)d_in[3];
    const float* beta  = (const float*)d_in[4];
    float* out = (float*)d_out;

    cudaFuncSetAttribute(attn_kernel, cudaFuncAttributeMaxDynamicSharedMemorySize, ATTN_SMEM_BYTES);
    cudaFuncSetAttribute(conv_kernel, cudaFuncAttributeMaxDynamicSharedMemorySize, CONV_SMEM_BYTES);

    attn_kernel<<<dim3(NTOK / MQ, BATCH), 128, ATTN_SMEM_BYTES>>>(x);
    conv_kernel<<<NCONVBLK, 256, CONV_SMEM_BYTES>>>(x, w, bias);
    stats_kernel<<<COUT, 256>>>(gamma, beta);
    bngelu_kernel<<<(COUT * NPOS) / 4 / 256, 256>>>(out);
}

// round 9
// speedup vs baseline: 1.6366x; 1.6366x over previous
#include <cuda_runtime.h>
#include <cuda_bf16.h>
#include <math.h>
#include <stdint.h>

// ---------------- problem constants ----------------
#define BATCH   8
#define CH      96
#define NTOK    3136
#define NPAD    3200          // 25 * 128
#define COUT    192
#define NPOS    (BATCH * NTOK)

#define MQT     128           // queries per CTA
#define NQT     25
#define KT      64            // keys per tile
#define NKT     49

// smem layout in bf16 elements; strides chosen conflict-free for ldmatrix
#define QSTR 104
#define KSTR 104
#define VSTR 72
#define SQH  0
#define SQL  (MQT * QSTR)              // 13312
#define SKH  (SQL + MQT * QSTR)        // 26624
#define SKL  (SKH + KT * KSTR)         // 33280
#define SVH  (SKL + KT * KSTR)         // 39936
#define SVL  (SVH + CH * VSTR)         // 46848
#define SM_ELEMS (SVL + CH * VSTR)     // 53760
#define ATT_SMEM_BYTES (SM_ELEMS * 2)  // 107520

// ---------------- scratch globals ----------------
__device__ __nv_bfloat16 g_th[BATCH * NPAD * CH];   // token-major hi [b][n][c]
__device__ __nv_bfloat16 g_tl[BATCH * NPAD * CH];   // token-major lo
__device__ __nv_bfloat16 g_chm[BATCH * CH * NTOK];  // channel-major hi [b][c][n]
__device__ __nv_bfloat16 g_clm[BATCH * CH * NTOK];  // channel-major lo
__device__ float g_norm[BATCH * NPAD];
__device__ float g_maxn[BATCH];
__device__ float g_xj[BATCH * CH * NTOK];
__device__ float g_y [COUT * NPOS];
#define CONV_POS 32
#define NCONVBLK (NPOS / CONV_POS)
__device__ float g_p1[NCONVBLK * COUT];
__device__ float g_p2[NCONVBLK * COUT];
__device__ float g_scale[COUT];
__device__ float g_shift[COUT];

// ---------------- warp MMA helpers (sm_80+ paths only; no arch-suffix instr) ----
__device__ __forceinline__ uint32_t smem_u32(const void* p) {
    uint32_t a;
    asm("{ .reg .u64 t; cvta.to.shared.u64 t, %1; cvt.u32.u64 %0, t; }" : "=r"(a) : "l"(p));
    return a;
}
__device__ __forceinline__ void ldmat4(uint32_t* r, uint32_t addr) {
    asm volatile("ldmatrix.sync.aligned.m8n8.x4.shared.b16 {%0,%1,%2,%3}, [%4];"
        : "=r"(r[0]), "=r"(r[1]), "=r"(r[2]), "=r"(r[3]) : "r"(addr));
}
__device__ __forceinline__ void mma_bf16(float* d, const uint32_t* a, const uint32_t* b) {
    asm volatile("mma.sync.aligned.m16n8k16.row.col.f32.bf16.bf16.f32 "
        "{%0,%1,%2,%3}, {%4,%5,%6,%7}, {%8,%9}, {%0,%1,%2,%3};"
        : "+f"(d[0]), "+f"(d[1]), "+f"(d[2]), "+f"(d[3])
        : "r"(a[0]), "r"(a[1]), "r"(a[2]), "r"(a[3]), "r"(b[0]), "r"(b[1]));
}

// =====================================================================
// prep: bf16 hi/lo split in token-major + channel-major layouts, norms
// grid (50, 8), 256 threads, each block 64 tokens x 96 ch
// =====================================================================
__global__ void __launch_bounds__(256) prep_kernel(const float* __restrict__ x)
{
    __shared__ float tile[CH][65];
    const int b = blockIdx.y;
    const int n0 = blockIdx.x * 64;
    const int tid = threadIdx.x;
    const bool valid = (n0 < NTOK);
    const float* xb = x + (size_t)b * CH * NTOK;

    for (int i = tid; i < CH * 16; i += 256) {
        int c = i >> 4;
        int q4 = (i & 15) << 2;
        float4 v = make_float4(0.f, 0.f, 0.f, 0.f);
        if (valid) v = *(const float4*)(xb + (size_t)c * NTOK + n0 + q4);
        tile[c][q4+0] = v.x; tile[c][q4+1] = v.y; tile[c][q4+2] = v.z; tile[c][q4+3] = v.w;
        if (valid) {
            uint32_t h0, h1, l0, l1;
            asm("cvt.rn.bf16x2.f32 %0, %1, %2;" : "=r"(h0) : "f"(v.y), "f"(v.x));
            asm("cvt.rn.bf16x2.f32 %0, %1, %2;" : "=r"(h1) : "f"(v.w), "f"(v.z));
            float r0 = v.x - __uint_as_float(h0 << 16);
            float r1 = v.y - __uint_as_float(h0 & 0xffff0000u);
            float r2 = v.z - __uint_as_float(h1 << 16);
            float r3 = v.w - __uint_as_float(h1 & 0xffff0000u);
            asm("cvt.rn.bf16x2.f32 %0, %1, %2;" : "=r"(l0) : "f"(r1), "f"(r0));
            asm("cvt.rn.bf16x2.f32 %0, %1, %2;" : "=r"(l1) : "f"(r3), "f"(r2));
            size_t gi = ((size_t)b * CH + c) * NTOK + n0 + q4;
            *(uint2*)(g_chm + gi) = make_uint2(h0, h1);
            *(uint2*)(g_clm + gi) = make_uint2(l0, l1);
        }
    }
    __syncthreads();
    // token-major rows (8 bf16 per store unit)
    for (int i = tid; i < 64 * 12; i += 256) {
        int tt = i / 12, u = i - tt * 12;
        int c0 = u * 8;
        uint32_t h[4], lo[4];
        #pragma unroll
        for (int k = 0; k < 4; k++) {
            float a  = tile[c0 + 2*k][tt];
            float bb = tile[c0 + 2*k + 1][tt];
            asm("cvt.rn.bf16x2.f32 %0, %1, %2;" : "=r"(h[k]) : "f"(bb), "f"(a));
            float ra = a  - __uint_as_float(h[k] << 16);
            float rb = bb - __uint_as_float(h[k] & 0xffff0000u);
            asm("cvt.rn.bf16x2.f32 %0, %1, %2;" : "=r"(lo[k]) : "f"(rb), "f"(ra));
        }
        size_t gi = ((size_t)b * NPAD + n0 + tt) * CH + c0;
        *(uint4*)(g_th + gi) = make_uint4(h[0], h[1], h[2], h[3]);
        *(uint4*)(g_tl + gi) = make_uint4(lo[0], lo[1], lo[2], lo[3]);
    }
    if (tid < 64) {
        float s = 0.f;
        #pragma unroll
        for (int c = 0; c < CH; c++) { float v = tile[c][tid]; s += v * v; }
        g_norm[b * NPAD + n0 + tid] = sqrtf(s);
    }
}

__global__ void __launch_bounds__(256) maxn_kernel()
{
    const int b = blockIdx.x, tid = threadIdx.x;
    __shared__ float red[256];
    float m = 0.f;
    for (int i = tid; i < NPAD; i += 256) m = fmaxf(m, g_norm[b * NPAD + i]);
    red[tid] = m; __syncthreads();
    for (int d = 128; d > 0; d >>= 1) { if (tid < d) red[tid] = fmaxf(red[tid], red[tid + d]); __syncthreads(); }
    if (tid == 0) g_maxn[b] = red[0];
}

// =====================================================================
// attention: mma.sync bf16 split-hi/lo, static-bound softmax, O in regs
// grid (25, 8), 256 threads (8 warps x 16 query rows)
// =====================================================================
__global__ void __launch_bounds__(256)
attn_mma_kernel(const float* __restrict__ x)
{
    extern __shared__ __nv_bfloat16 sm[];
    const uint32_t sb = smem_u32(sm);
    const int tid  = threadIdx.x;
    const int wid  = tid >> 5;
    const int lane = tid & 31;
    const int g    = lane >> 2;     // groupID: D rows g, g+8
    const int tig  = lane & 3;
    const int b    = blockIdx.y;
    const int n0   = blockIdx.x * MQT;

    // ---- load Q tile (hi/lo) 128 x 96
    for (int i = tid; i < MQT * 12; i += 256) {
        int r = i / 12, u = i - r * 12;
        size_t src = ((size_t)(b * NPAD + n0 + r)) * CH + u * 8;
        *(uint4*)(sm + SQH + r * QSTR + u * 8) = *(const uint4*)(g_th + src);
        *(uint4*)(sm + SQL + r * QSTR + u * 8) = *(const uint4*)(g_tl + src);
    }
    const float maxn = g_maxn[b];
    const float E0 = g_norm[b * NPAD + n0 + wid * 16 + g]     * maxn;
    const float E1 = g_norm[b * NPAD + n0 + wid * 16 + g + 8] * maxn;

    float o[12][4];
    #pragma unroll
    for (int j = 0; j < 12; j++)
        #pragma unroll
        for (int q = 0; q < 4; q++) o[j][q] = 0.f;
    float l0 = 0.f, l1 = 0.f;

    const int l16 = lane & 15;
    const int hf8 = (lane >> 4) * 8;
    const uint32_t qbase = sb + 2u * (uint32_t)(SQH + (wid * 16 + l16) * QSTR + hf8);
    const uint32_t qlo   = 2u * (uint32_t)(SQL - SQH);
    const uint32_t kbase = sb + 2u * (uint32_t)(SKH + l16 * KSTR + hf8);
    const uint32_t klo   = 2u * (uint32_t)(SKL - SKH);
    const uint32_t vbase = sb + 2u * (uint32_t)(SVH + l16 * VSTR + hf8);
    const uint32_t vlo   = 2u * (uint32_t)(SVL - SVH);

    for (int t = 0; t < NKT; t++) {
        __syncthreads();
        // K tile: 64 tok x 96 ch (hi/lo)
        for (int i = tid; i < KT * 12; i += 256) {
            int r = i / 12, u = i - r * 12;
            size_t src = ((size_t)(b * NPAD + t * KT + r)) * CH + u * 8;
            *(uint4*)(sm + SKH + r * KSTR + u * 8) = *(const uint4*)(g_th + src);
            *(uint4*)(sm + SKL + r * KSTR + u * 8) = *(const uint4*)(g_tl + src);
        }
        // V tile: 96 ch x 64 tok (hi/lo)
        for (int i = tid; i < CH * 8; i += 256) {
            int c = i >> 3, u = i & 7;
            size_t src = ((size_t)(b * CH + c)) * NTOK + t * KT + u * 8;
            *(uint4*)(sm + SVH + c * VSTR + u * 8) = *(const uint4*)(g_chm + src);
            *(uint4*)(sm + SVL + c * VSTR + u * 8) = *(const uint4*)(g_clm + src);
        }
        __syncthreads();

        // ---- S = Q K^T (16 x 64 per warp), 3-term split
        float s[8][4];
        #pragma unroll
        for (int j = 0; j < 8; j++)
            #pragma unroll
            for (int q = 0; q < 4; q++) s[j][q] = 0.f;

        #pragma unroll
        for (int kb = 0; kb < 6; kb++) {
            uint32_t qh[4], ql[4];
            ldmat4(qh, qbase + kb * 32);
            ldmat4(ql, qbase + qlo + kb * 32);
            #pragma unroll
            for (int nb = 0; nb < 4; nb++) {
                uint32_t bh[4], blr[4];
                uint32_t ka = kbase + (uint32_t)(nb * 16 * KSTR * 2) + kb * 32;
                ldmat4(bh, ka);
                ldmat4(blr, ka + klo);
                uint32_t b0[2] = {bh[0], bh[2]},  b1[2] = {bh[1], bh[3]};
                uint32_t c0[2] = {blr[0], blr[2]}, c1[2] = {blr[1], blr[3]};
                mma_bf16(s[2*nb],   qh, b0);
                mma_bf16(s[2*nb+1], qh, b1);
                mma_bf16(s[2*nb],   qh, c0);
                mma_bf16(s[2*nb+1], qh, c1);
                mma_bf16(s[2*nb],   ql, b0);
                mma_bf16(s[2*nb+1], ql, b1);
            }
        }

        // ---- softmax p = exp(s - E); pack P hi/lo A-fragments in registers
        uint32_t pha[4][4], pla[4][4];
        #pragma unroll
        for (int j = 0; j < 8; j++) {
            float p0 = __expf(s[j][0] - E0);
            float p1 = __expf(s[j][1] - E0);
            float p2 = __expf(s[j][2] - E1);
            float p3 = __expf(s[j][3] - E1);
            l0 += p0 + p1; l1 += p2 + p3;
            uint32_t h01, h23, q01, q23;
            asm("cvt.rn.bf16x2.f32 %0, %1, %2;" : "=r"(h01) : "f"(p1), "f"(p0));
            asm("cvt.rn.bf16x2.f32 %0, %1, %2;" : "=r"(h23) : "f"(p3), "f"(p2));
            float r0 = p0 - __uint_as_float(h01 << 16);
            float r1 = p1 - __uint_as_float(h01 & 0xffff0000u);
            float r2 = p2 - __uint_as_float(h23 << 16);
            float r3 = p3 - __uint_as_float(h23 & 0xffff0000u);
            asm("cvt.rn.bf16x2.f32 %0, %1, %2;" : "=r"(q01) : "f"(r1), "f"(r0));
            asm("cvt.rn.bf16x2.f32 %0, %1, %2;" : "=r"(q23) : "f"(r3), "f"(r2));
            int kb = j >> 1;
            if ((j & 1) == 0) { pha[kb][0] = h01; pha[kb][1] = h23; pla[kb][0] = q01; pla[kb][1] = q23; }
            else              { pha[kb][2] = h01; pha[kb][3] = h23; pla[kb][2] = q01; pla[kb][3] = q23; }
        }

        // ---- O += P V (16 x 96 per warp), 3-term split
        #pragma unroll
        for (int kb = 0; kb < 4; kb++) {
            #pragma unroll
            for (int vb = 0; vb < 6; vb++) {
                uint32_t vh[4], vl[4];
                uint32_t va = vbase + (uint32_t)(vb * 16 * VSTR * 2) + kb * 32;
                ldmat4(vh, va);
                ldmat4(vl, va + vlo);
                uint32_t b0[2] = {vh[0], vh[2]}, b1[2] = {vh[1], vh[3]};
                uint32_t c0[2] = {vl[0], vl[2]}, c1[2] = {vl[1], vl[3]};
                mma_bf16(o[2*vb],   pha[kb], b0);
                mma_bf16(o[2*vb+1], pha[kb], b1);
                mma_bf16(o[2*vb],   pha[kb], c0);
                mma_bf16(o[2*vb+1], pha[kb], c1);
                mma_bf16(o[2*vb],   pla[kb], b0);
                mma_bf16(o[2*vb+1], pla[kb], b1);
            }
        }
    }

    // ---- row sums across the quad (lanes sharing groupID)
    l0 += __shfl_xor_sync(0xffffffffu, l0, 1);
    l0 += __shfl_xor_sync(0xffffffffu, l0, 2);
    l1 += __shfl_xor_sync(0xffffffffu, l1, 1);
    l1 += __shfl_xor_sync(0xffffffffu, l1, 2);
    const float i0 = 1.f / l0, i1 = 1.f / l1;

    __syncthreads();
    float* stage = (float*)sm;   // 128 rows x stride 100 floats (51.2KB < Q area)
    #pragma unroll
    for (int j = 0; j < 12; j++) {
        int c = 8 * j + 2 * tig;
        stage[(wid * 16 + g) * 100 + c]         = o[j][0] * i0;
        stage[(wid * 16 + g) * 100 + c + 1]     = o[j][1] * i0;
        stage[(wid * 16 + g + 8) * 100 + c]     = o[j][2] * i1;
        stage[(wid * 16 + g + 8) * 100 + c + 1] = o[j][3] * i1;
    }
    __syncthreads();

    const float* xb = x + (size_t)b * CH * NTOK;
    for (int i = tid; i < CH * 32; i += 256) {
        int c = i >> 5, q4 = (i & 31) << 2;
        int n = n0 + q4;
        if (n < NTOK) {
            float4 xv = *(const float4*)(xb + (size_t)c * NTOK + n);
            float4 ov;
            ov.x = fmaxf(xv.x - stage[(q4 + 0) * 100 + c], 0.f);
            ov.y = fmaxf(xv.y - stage[(q4 + 1) * 100 + c], 0.f);
            ov.z = fmaxf(xv.z - stage[(q4 + 2) * 100 + c], 0.f);
            ov.w = fmaxf(xv.w - stage[(q4 + 3) * 100 + c], 0.f);
            *(float4*)(g_xj + ((size_t)b * CH + c) * NTOK + n) = ov;
        }
    }
}

// =====================================================================
// conv / stats / bngelu — unchanged from the passing R1 kernel
// =====================================================================
#define WS_STRIDE 193
#define CS_STRIDE 33
#define CONV_SMEM_FLOATS (COUT * WS_STRIDE + (2*CH) * CS_STRIDE)
#define CONV_SMEM_BYTES  (CONV_SMEM_FLOATS * 4)

__global__ void __launch_bounds__(256, 1)
conv_kernel(const float* __restrict__ x, const float* __restrict__ w,
            const float* __restrict__ bias)
{
    extern __shared__ float smf[];
    float* Ws = smf;
    float* cs = smf + COUT * WS_STRIDE;

    const int tid = threadIdx.x;
    for (int i = tid; i < COUT * (2 * CH); i += 256) {
        int o = i / (2 * CH), k = i - o * (2 * CH);
        Ws[o * WS_STRIDE + k] = w[i];
    }
    const int p0 = blockIdx.x * CONV_POS;
    const int b  = p0 / NTOK;
    const int n0 = p0 - b * NTOK;

    for (int i = tid; i < CH * CONV_POS; i += 256) {
        int k = i / CONV_POS, pp = i - k * CONV_POS;
        size_t gi = ((size_t)b * CH + k) * NTOK + n0 + pp;
        cs[k * CS_STRIDE + pp]        = x[gi];
        cs[(k + CH) * CS_STRIDE + pp] = g_xj[gi];
    }
    __syncthreads();

    const int to = tid >> 3;
    const int tp = tid & 7;

    float acc[6][4];
    #pragma unroll
    for (int j = 0; j < 6; j++)
        #pragma unroll
        for (int q = 0; q < 4; q++) acc[j][q] = 0.f;

    for (int k = 0; k < 2 * CH; k++) {
        float bb[4];
        #pragma unroll
        for (int q = 0; q < 4; q++) bb[q] = cs[k * CS_STRIDE + tp * 4 + q];
        #pragma unroll
        for (int j = 0; j < 6; j++) {
            float a = Ws[(to * 6 + j) * WS_STRIDE + k];
            #pragma unroll
            for (int q = 0; q < 4; q++) acc[j][q] += a * bb[q];
        }
    }
    #pragma unroll
    for (int j = 0; j < 6; j++) {
        const int o = to * 6 + j;
        const float bi = bias[o];
        float a1 = 0.f, a2 = 0.f;
        #pragma unroll
        for (int q = 0; q < 4; q++) {
            float y = acc[j][q] + bi;
            g_y[(size_t)o * NPOS + p0 + tp * 4 + q] = y;
            a1 += y;
            a2 += y * y;
        }
        #pragma unroll
        for (int d = 4; d > 0; d >>= 1) {
            a1 += __shfl_down_sync(0xffffffffu, a1, d, 8);
            a2 += __shfl_down_sync(0xffffffffu, a2, d, 8);
        }
        if (tp == 0) {
            g_p1[blockIdx.x * COUT + o] = a1;
            g_p2[blockIdx.x * COUT + o] = a2;
        }
    }
}

__global__ void __launch_bounds__(256)
stats_kernel(const float* __restrict__ gamma, const float* __restrict__ beta)
{
    const int o = blockIdx.x;
    const int tid = threadIdx.x;
    float s1 = 0.f, s2 = 0.f;
    for (int i = tid; i < NCONVBLK; i += 256) {
        s1 += g_p1[i * COUT + o];
        s2 += g_p2[i * COUT + o];
    }
    __shared__ float r1[256], r2[256];
    r1[tid] = s1; r2[tid] = s2;
    __syncthreads();
    for (int d = 128; d > 0; d >>= 1) {
        if (tid < d) { r1[tid] += r1[tid + d]; r2[tid] += r2[tid + d]; }
        __syncthreads();
    }
    if (tid == 0) {
        const float invN = 1.f / (float)NPOS;
        float mean = r1[0] * invN;
        float var  = r2[0] * invN - mean * mean;
        float rstd = rsqrtf(var + 1e-5f);
        float gg = gamma[o] * rstd;
        g_scale[o] = gg;
        g_shift[o] = beta[o] - mean * gg;
    }
}

__global__ void __launch_bounds__(256)
bngelu_kernel(float* __restrict__ out)
{
    const int idx4 = blockIdx.x * 256 + threadIdx.x;
    const int base = idx4 * 4;
    const int o = base / NPOS;
    const int p = base - o * NPOS;
    const int b = p / NTOK;
    const int n = p - b * NTOK;

    float4 v = *(const float4*)(g_y + base);
    const float sc = g_scale[o], sh = g_shift[o];
    float r[4] = {v.x, v.y, v.z, v.w};
    #pragma unroll
    for (int i = 0; i < 4; i++) {
        float u = r[i] * sc + sh;
        r[i] = 0.5f * u * (1.f + erff(u * 0.70710678118654752f));
    }
    float4 ov = {r[0], r[1], r[2], r[3]};
    *(float4*)(out + (size_t)b * (COUT * NTOK) + (size_t)o * NTOK + n) = ov;
}

// =====================================================================
extern "C" void kernel_launch(void* const* d_in, const int* in_sizes, int n_in,
                              void* d_out, int out_size)
{
    const float* x     = (const float*)d_in[0];
    const float* w     = (const float*)d_in[1];
    const float* bias  = (const float*)d_in[2];
    const float* gamma = (const float*)d_in[3];
    const float* beta  = (const float*)d_in[4];
    float* out = (float*)d_out;

    cudaFuncSetAttribute(attn_mma_kernel, cudaFuncAttributeMaxDynamicSharedMemorySize, ATT_SMEM_BYTES);
    cudaFuncSetAttribute(conv_kernel,     cudaFuncAttributeMaxDynamicSharedMemorySize, CONV_SMEM_BYTES);

    prep_kernel<<<dim3(NPAD / 64, BATCH), 256>>>(x);
    maxn_kernel<<<BATCH, 256>>>();
    attn_mma_kernel<<<dim3(NQT, BATCH), 256, ATT_SMEM_BYTES>>>(x);
    conv_kernel<<<NCONVBLK, 256, CONV_SMEM_BYTES>>>(x, w, bias);
    stats_kernel<<<COUT, 256>>>(gamma, beta);
    bngelu_kernel<<<(COUT * NPOS) / 4 / 256, 256>>>(out);
}

// round 12
// speedup vs baseline: 2.0006x; 1.2224x over previous
#include <cuda_runtime.h>
#include <cuda_bf16.h>
#include <math.h>
#include <stdint.h>

// ---------------- problem constants ----------------
#define BATCH   8
#define CH      96
#define NTOK    3136
#define NPAD    3200          // 25 * 128
#define COUT    192
#define NPOS    (BATCH * NTOK)

#define MQT     128           // queries per CTA
#define NQT     25
#define KT      64            // keys per tile
#define NKT     49

// smem layout in bf16 elements; strides conflict-free for ldmatrix
#define QSTR 104
#define KSTR 104
#define VSTR 72
#define SQH  0
#define SQL  (MQT * QSTR)                  // 13312
#define KV0  (SQL + MQT * QSTR)            // 26624  (start of double buffers)
#define KPART (KT * KSTR)                  // 6656 elems (one K operand)
#define VPART (CH * VSTR)                  // 6912 elems (one V operand)
#define BUFSZ (2 * KPART + 2 * VPART)      // 27136 elems per stage
#define SM_ELEMS (KV0 + 2 * BUFSZ)         // 80896
#define ATT_SMEM_BYTES (SM_ELEMS * 2)      // 161792

// ---------------- scratch globals ----------------
__device__ __nv_bfloat16 g_th[BATCH * NPAD * CH];   // token-major hi [b][n][c]
__device__ __nv_bfloat16 g_tl[BATCH * NPAD * CH];   // token-major lo
__device__ __nv_bfloat16 g_chm[BATCH * CH * NTOK];  // channel-major hi [b][c][n]
__device__ __nv_bfloat16 g_clm[BATCH * CH * NTOK];  // channel-major lo
__device__ float g_norm[BATCH * NPAD];
__device__ float g_maxn[BATCH];
__device__ float g_xj[BATCH * CH * NTOK];
__device__ float g_y [COUT * NPOS];
#define NCONVBLK 784
__device__ float g_p1[NCONVBLK * COUT];
__device__ float g_p2[NCONVBLK * COUT];
__device__ float g_scale[COUT];
__device__ float g_shift[COUT];

// ---------------- warp MMA / async-copy helpers (sm_80+ baseline PTX) ----
__device__ __forceinline__ uint32_t smem_u32(const void* p) {
    uint32_t a;
    asm("{ .reg .u64 t; cvta.to.shared.u64 t, %1; cvt.u32.u64 %0, t; }" : "=r"(a) : "l"(p));
    return a;
}
__device__ __forceinline__ void ldmat4(uint32_t* r, uint32_t addr) {
    asm volatile("ldmatrix.sync.aligned.m8n8.x4.shared.b16 {%0,%1,%2,%3}, [%4];"
        : "=r"(r[0]), "=r"(r[1]), "=r"(r[2]), "=r"(r[3]) : "r"(addr));
}
__device__ __forceinline__ void mma_bf16(float* d, const uint32_t* a, const uint32_t* b) {
    asm volatile("mma.sync.aligned.m16n8k16.row.col.f32.bf16.bf16.f32 "
        "{%0,%1,%2,%3}, {%4,%5,%6,%7}, {%8,%9}, {%0,%1,%2,%3};"
        : "+f"(d[0]), "+f"(d[1]), "+f"(d[2]), "+f"(d[3])
        : "r"(a[0]), "r"(a[1]), "r"(a[2]), "r"(a[3]), "r"(b[0]), "r"(b[1]));
}
#define CPA16(dst, src) asm volatile("cp.async.cg.shared.global [%0], [%1], 16;" :: "r"(dst), "l"(src) : "memory")
#define CPA_COMMIT()    asm volatile("cp.async.commit_group;" ::: "memory")
#define CPA_WAIT1()     asm volatile("cp.async.wait_group 1;" ::: "memory")
#define CPA_WAIT0()     asm volatile("cp.async.wait_group 0;" ::: "memory")

// =====================================================================
// prep: bf16 hi/lo split in token-major + channel-major layouts, norms
// grid (50, 8), 256 threads, each block 64 tokens x 96 ch
// =====================================================================
__global__ void __launch_bounds__(256) prep_kernel(const float* __restrict__ x)
{
    __shared__ float tile[CH][65];
    const int b = blockIdx.y;
    const int n0 = blockIdx.x * 64;
    const int tid = threadIdx.x;
    const bool valid = (n0 < NTOK);
    const float* xb = x + (size_t)b * CH * NTOK;

    for (int i = tid; i < CH * 16; i += 256) {
        int c = i >> 4;
        int q4 = (i & 15) << 2;
        float4 v = make_float4(0.f, 0.f, 0.f, 0.f);
        if (valid) v = *(const float4*)(xb + (size_t)c * NTOK + n0 + q4);
        tile[c][q4+0] = v.x; tile[c][q4+1] = v.y; tile[c][q4+2] = v.z; tile[c][q4+3] = v.w;
        if (valid) {
            uint32_t h0, h1, l0, l1;
            asm("cvt.rn.bf16x2.f32 %0, %1, %2;" : "=r"(h0) : "f"(v.y), "f"(v.x));
            asm("cvt.rn.bf16x2.f32 %0, %1, %2;" : "=r"(h1) : "f"(v.w), "f"(v.z));
            float r0 = v.x - __uint_as_float(h0 << 16);
            float r1 = v.y - __uint_as_float(h0 & 0xffff0000u);
            float r2 = v.z - __uint_as_float(h1 << 16);
            float r3 = v.w - __uint_as_float(h1 & 0xffff0000u);
            asm("cvt.rn.bf16x2.f32 %0, %1, %2;" : "=r"(l0) : "f"(r1), "f"(r0));
            asm("cvt.rn.bf16x2.f32 %0, %1, %2;" : "=r"(l1) : "f"(r3), "f"(r2));
            size_t gi = ((size_t)b * CH + c) * NTOK + n0 + q4;
            *(uint2*)(g_chm + gi) = make_uint2(h0, h1);
            *(uint2*)(g_clm + gi) = make_uint2(l0, l1);
        }
    }
    __syncthreads();
    for (int i = tid; i < 64 * 12; i += 256) {
        int tt = i / 12, u = i - tt * 12;
        int c0 = u * 8;
        uint32_t h[4], lo[4];
        #pragma unroll
        for (int k = 0; k < 4; k++) {
            float a  = tile[c0 + 2*k][tt];
            float bb = tile[c0 + 2*k + 1][tt];
            asm("cvt.rn.bf16x2.f32 %0, %1, %2;" : "=r"(h[k]) : "f"(bb), "f"(a));
            float ra = a  - __uint_as_float(h[k] << 16);
            float rb = bb - __uint_as_float(h[k] & 0xffff0000u);
            asm("cvt.rn.bf16x2.f32 %0, %1, %2;" : "=r"(lo[k]) : "f"(rb), "f"(ra));
        }
        size_t gi = ((size_t)b * NPAD + n0 + tt) * CH + c0;
        *(uint4*)(g_th + gi) = make_uint4(h[0], h[1], h[2], h[3]);
        *(uint4*)(g_tl + gi) = make_uint4(lo[0], lo[1], lo[2], lo[3]);
    }
    if (tid < 64) {
        float s = 0.f;
        #pragma unroll
        for (int c = 0; c < CH; c++) { float v = tile[c][tid]; s += v * v; }
        g_norm[b * NPAD + n0 + tid] = sqrtf(s);
    }
}

__global__ void __launch_bounds__(256) maxn_kernel()
{
    const int b = blockIdx.x, tid = threadIdx.x;
    __shared__ float red[256];
    float m = 0.f;
    for (int i = tid; i < NPAD; i += 256) m = fmaxf(m, g_norm[b * NPAD + i]);
    red[tid] = m; __syncthreads();
    for (int d = 128; d > 0; d >>= 1) { if (tid < d) red[tid] = fmaxf(red[tid], red[tid + d]); __syncthreads(); }
    if (tid == 0) g_maxn[b] = red[0];
}

// =====================================================================
// attention: mma.sync bf16 split-hi/lo, static-bound softmax, O in regs
// cp.async double-buffered K/V. grid (25, 8), 256 threads
// =====================================================================
__global__ void __launch_bounds__(256)
attn_mma_kernel(const float* __restrict__ x)
{
    extern __shared__ __nv_bfloat16 sm[];
    const uint32_t sb = smem_u32(sm);
    const int tid  = threadIdx.x;
    const int wid  = tid >> 5;
    const int lane = tid & 31;
    const int g    = lane >> 2;
    const int tig  = lane & 3;
    const int b    = blockIdx.y;
    const int n0   = blockIdx.x * MQT;

    // ---- load Q tile (hi/lo) 128 x 96 (plain stores)
    for (int i = tid; i < MQT * 12; i += 256) {
        int r = i / 12, u = i - r * 12;
        size_t src = ((size_t)(b * NPAD + n0 + r)) * CH + u * 8;
        *(uint4*)(sm + SQH + r * QSTR + u * 8) = *(const uint4*)(g_th + src);
        *(uint4*)(sm + SQL + r * QSTR + u * 8) = *(const uint4*)(g_tl + src);
    }

    // ---- async prefetch of KV tile t into buffer d
    auto issue_kv = [&](int t, int d) {
        const int koff = KV0 + d * BUFSZ;
        const int voff = koff + 2 * KPART;
        const size_t ksrc = ((size_t)(b * NPAD + t * KT)) * CH;
        for (int i = tid; i < KT * 12; i += 256) {
            int r = i / 12, u = i - r * 12;
            uint32_t dst = sb + 2u * (uint32_t)(koff + r * KSTR + u * 8);
            CPA16(dst,                 (const void*)(g_th + ksrc + r * CH + u * 8));
            CPA16(dst + 2u * KPART,    (const void*)(g_tl + ksrc + r * CH + u * 8));
        }
        const size_t vsrc = (size_t)b * CH * NTOK + (size_t)t * KT;
        for (int i = tid; i < CH * 8; i += 256) {
            int c = i >> 3, u = i & 7;
            uint32_t dst = sb + 2u * (uint32_t)(voff + c * VSTR + u * 8);
            CPA16(dst,                 (const void*)(g_chm + vsrc + (size_t)c * NTOK + u * 8));
            CPA16(dst + 2u * VPART,    (const void*)(g_clm + vsrc + (size_t)c * NTOK + u * 8));
        }
    };

    issue_kv(0, 0);
    CPA_COMMIT();

    const float maxn = g_maxn[b];
    const float E0 = g_norm[b * NPAD + n0 + wid * 16 + g]     * maxn;
    const float E1 = g_norm[b * NPAD + n0 + wid * 16 + g + 8] * maxn;

    float o[12][4];
    #pragma unroll
    for (int j = 0; j < 12; j++)
        #pragma unroll
        for (int q = 0; q < 4; q++) o[j][q] = 0.f;
    float l0 = 0.f, l1 = 0.f;

    const int l16 = lane & 15;
    const int hf8 = (lane >> 4) * 8;
    const uint32_t qbase = sb + 2u * (uint32_t)(SQH + (wid * 16 + l16) * QSTR + hf8);
    const uint32_t qlo   = 2u * (uint32_t)(SQL - SQH);
    const uint32_t klo   = 2u * (uint32_t)KPART;
    const uint32_t vlo   = 2u * (uint32_t)VPART;

    for (int t = 0; t < NKT; t++) {
        if (t + 1 < NKT) {
            issue_kv(t + 1, (t + 1) & 1);
            CPA_COMMIT();
            CPA_WAIT1();
        } else {
            CPA_WAIT0();
        }
        __syncthreads();

        const int koff = KV0 + (t & 1) * BUFSZ;
        const uint32_t kbase = sb + 2u * (uint32_t)(koff + l16 * KSTR + hf8);
        const uint32_t vbase = sb + 2u * (uint32_t)(koff + 2 * KPART + l16 * VSTR + hf8);

        // ---- S = Q K^T (16 x 64 per warp), 3-term split
        float s[8][4];
        #pragma unroll
        for (int j = 0; j < 8; j++)
            #pragma unroll
            for (int q = 0; q < 4; q++) s[j][q] = 0.f;

        #pragma unroll
        for (int kb = 0; kb < 6; kb++) {
            uint32_t qh[4], ql[4];
            ldmat4(qh, qbase + kb * 32);
            ldmat4(ql, qbase + qlo + kb * 32);
            #pragma unroll
            for (int nb = 0; nb < 4; nb++) {
                uint32_t bh[4], blr[4];
                uint32_t ka = kbase + (uint32_t)(nb * 16 * KSTR * 2) + kb * 32;
                ldmat4(bh, ka);
                ldmat4(blr, ka + klo);
                uint32_t b0[2] = {bh[0], bh[2]},  b1[2] = {bh[1], bh[3]};
                uint32_t c0[2] = {blr[0], blr[2]}, c1[2] = {blr[1], blr[3]};
                mma_bf16(s[2*nb],   qh, b0);
                mma_bf16(s[2*nb+1], qh, b1);
                mma_bf16(s[2*nb],   qh, c0);
                mma_bf16(s[2*nb+1], qh, c1);
                mma_bf16(s[2*nb],   ql, b0);
                mma_bf16(s[2*nb+1], ql, b1);
            }
        }

        // ---- softmax p = exp(s - E); pack P hi/lo A-fragments in registers
        uint32_t pha[4][4], pla[4][4];
        #pragma unroll
        for (int j = 0; j < 8; j++) {
            float p0 = __expf(s[j][0] - E0);
            float p1 = __expf(s[j][1] - E0);
            float p2 = __expf(s[j][2] - E1);
            float p3 = __expf(s[j][3] - E1);
            l0 += p0 + p1; l1 += p2 + p3;
            uint32_t h01, h23, q01, q23;
            asm("cvt.rn.bf16x2.f32 %0, %1, %2;" : "=r"(h01) : "f"(p1), "f"(p0));
            asm("cvt.rn.bf16x2.f32 %0, %1, %2;" : "=r"(h23) : "f"(p3), "f"(p2));
            float r0 = p0 - __uint_as_float(h01 << 16);
            float r1 = p1 - __uint_as_float(h01 & 0xffff0000u);
            float r2 = p2 - __uint_as_float(h23 << 16);
            float r3 = p3 - __uint_as_float(h23 & 0xffff0000u);
            asm("cvt.rn.bf16x2.f32 %0, %1, %2;" : "=r"(q01) : "f"(r1), "f"(r0));
            asm("cvt.rn.bf16x2.f32 %0, %1, %2;" : "=r"(q23) : "f"(r3), "f"(r2));
            int kb = j >> 1;
            if ((j & 1) == 0) { pha[kb][0] = h01; pha[kb][1] = h23; pla[kb][0] = q01; pla[kb][1] = q23; }
            else              { pha[kb][2] = h01; pha[kb][3] = h23; pla[kb][2] = q01; pla[kb][3] = q23; }
        }

        // ---- O += P V (16 x 96 per warp), 3-term split
        #pragma unroll
        for (int kb = 0; kb < 4; kb++) {
            #pragma unroll
            for (int vb = 0; vb < 6; vb++) {
                uint32_t vh[4], vl[4];
                uint32_t va = vbase + (uint32_t)(vb * 16 * VSTR * 2) + kb * 32;
                ldmat4(vh, va);
                ldmat4(vl, va + vlo);
                uint32_t b0[2] = {vh[0], vh[2]}, b1[2] = {vh[1], vh[3]};
                uint32_t c0[2] = {vl[0], vl[2]}, c1[2] = {vl[1], vl[3]};
                mma_bf16(o[2*vb],   pha[kb], b0);
                mma_bf16(o[2*vb+1], pha[kb], b1);
                mma_bf16(o[2*vb],   pha[kb], c0);
                mma_bf16(o[2*vb+1], pha[kb], c1);
                mma_bf16(o[2*vb],   pla[kb], b0);
                mma_bf16(o[2*vb+1], pla[kb], b1);
            }
        }
        __syncthreads();
    }

    // ---- row sums across the quad
    l0 += __shfl_xor_sync(0xffffffffu, l0, 1);
    l0 += __shfl_xor_sync(0xffffffffu, l0, 2);
    l1 += __shfl_xor_sync(0xffffffffu, l1, 1);
    l1 += __shfl_xor_sync(0xffffffffu, l1, 2);
    const float i0 = 1.f / l0, i1 = 1.f / l1;

    float* stage = (float*)sm;   // 128 x 100 floats, reuses Q region
    #pragma unroll
    for (int j = 0; j < 12; j++) {
        int c = 8 * j + 2 * tig;
        stage[(wid * 16 + g) * 100 + c]         = o[j][0] * i0;
        stage[(wid * 16 + g) * 100 + c + 1]     = o[j][1] * i0;
        stage[(wid * 16 + g + 8) * 100 + c]     = o[j][2] * i1;
        stage[(wid * 16 + g + 8) * 100 + c + 1] = o[j][3] * i1;
    }
    __syncthreads();

    const float* xb = x + (size_t)b * CH * NTOK;
    for (int i = tid; i < CH * 32; i += 256) {
        int c = i >> 5, q4 = (i & 31) << 2;
        int n = n0 + q4;
        if (n < NTOK) {
            float4 xv = *(const float4*)(xb + (size_t)c * NTOK + n);
            float4 ov;
            ov.x = fmaxf(xv.x - stage[(q4 + 0) * 100 + c], 0.f);
            ov.y = fmaxf(xv.y - stage[(q4 + 1) * 100 + c], 0.f);
            ov.z = fmaxf(xv.z - stage[(q4 + 2) * 100 + c], 0.f);
            ov.w = fmaxf(xv.w - stage[(q4 + 3) * 100 + c], 0.f);
            *(float4*)(g_xj + ((size_t)b * CH + c) * NTOK + n) = ov;
        }
    }
}

// =====================================================================
// conv: grid (98, 2), 256 threads, occ 2.
// block = 96 out-channels (half of W, 74 KB smem) x 256 positions in
// 8 chunks of 32. W loaded once per block -> 8x less W traffic.
// =====================================================================
#define WTILE 96
#define WSTR  193
#define CSTR  33
#define CONV_SMEM_FLOATS (WTILE * WSTR + (2*CH) * CSTR)
#define CONV_SMEM_BYTES  (CONV_SMEM_FLOATS * 4)

__global__ void __launch_bounds__(256, 2)
conv_kernel(const float* __restrict__ x, const float* __restrict__ w,
            const float* __restrict__ bias)
{
    extern __shared__ float smf[];
    float* Ws = smf;                    // 96 x 193
    float* cs = smf + WTILE * WSTR;     // 192 x 33

    const int tid = threadIdx.x;
    const int oh  = blockIdx.y;         // output half
    const int obase = oh * WTILE;

    for (int i = tid; i < WTILE * (2 * CH); i += 256) {
        int o = i / (2 * CH), k = i - o * (2 * CH);
        Ws[o * WSTR + k] = w[(obase + o) * (2 * CH) + k];
    }

    const int to = tid >> 3;            // 0..31, owns 3 out channels
    const int tp = tid & 7;             // 0..7,  owns 4 positions

    for (int chunk = 0; chunk < 8; chunk++) {
        const int p0 = blockIdx.x * 256 + chunk * 32;
        const int b  = p0 / NTOK;
        const int n0 = p0 - b * NTOK;

        __syncthreads();
        for (int i = tid; i < CH * 32; i += 256) {
            int k = i >> 5, pp = i & 31;
            size_t gi = ((size_t)b * CH + k) * NTOK + n0 + pp;
            cs[k * CSTR + pp]        = x[gi];
            cs[(k + CH) * CSTR + pp] = g_xj[gi];
        }
        __syncthreads();

        float acc[3][4];
        #pragma unroll
        for (int j = 0; j < 3; j++)
            #pragma unroll
            for (int q = 0; q < 4; q++) acc[j][q] = 0.f;

        for (int k = 0; k < 2 * CH; k++) {
            float bb[4];
            #pragma unroll
            for (int q = 0; q < 4; q++) bb[q] = cs[k * CSTR + tp * 4 + q];
            #pragma unroll
            for (int j = 0; j < 3; j++) {
                float a = Ws[(to * 3 + j) * WSTR + k];
                #pragma unroll
                for (int q = 0; q < 4; q++) acc[j][q] += a * bb[q];
            }
        }

        const int pb = blockIdx.x * 8 + chunk;
        #pragma unroll
        for (int j = 0; j < 3; j++) {
            const int o = obase + to * 3 + j;
            const float bi = bias[o];
            float a1 = 0.f, a2 = 0.f;
            #pragma unroll
            for (int q = 0; q < 4; q++) {
                float y = acc[j][q] + bi;
                g_y[(size_t)o * NPOS + p0 + tp * 4 + q] = y;
                a1 += y;
                a2 += y * y;
            }
            #pragma unroll
            for (int d = 4; d > 0; d >>= 1) {
                a1 += __shfl_down_sync(0xffffffffu, a1, d, 8);
                a2 += __shfl_down_sync(0xffffffffu, a2, d, 8);
            }
            if (tp == 0) {
                g_p1[pb * COUT + o] = a1;
                g_p2[pb * COUT + o] = a2;
            }
        }
    }
}

__global__ void __launch_bounds__(256)
stats_kernel(const float* __restrict__ gamma, const float* __restrict__ beta)
{
    const int o = blockIdx.x;
    const int tid = threadIdx.x;
    float s1 = 0.f, s2 = 0.f;
    for (int i = tid; i < NCONVBLK; i += 256) {
        s1 += g_p1[i * COUT + o];
        s2 += g_p2[i * COUT + o];
    }
    __shared__ float r1[256], r2[256];
    r1[tid] = s1; r2[tid] = s2;
    __syncthreads();
    for (int d = 128; d > 0; d >>= 1) {
        if (tid < d) { r1[tid] += r1[tid + d]; r2[tid] += r2[tid + d]; }
        __syncthreads();
    }
    if (tid == 0) {
        const float invN = 1.f / (float)NPOS;
        float mean = r1[0] * invN;
        float var  = r2[0] * invN - mean * mean;
        float rstd = rsqrtf(var + 1e-5f);
        float gg = gamma[o] * rstd;
        g_scale[o] = gg;
        g_shift[o] = beta[o] - mean * gg;
    }
}

__global__ void __launch_bounds__(256)
bngelu_kernel(float* __restrict__ out)
{
    const int idx4 = blockIdx.x * 256 + threadIdx.x;
    const int base = idx4 * 4;
    const int o = base / NPOS;
    const int p = base - o * NPOS;
    const int b = p / NTOK;
    const int n = p - b * NTOK;

    float4 v = *(const float4*)(g_y + base);
    const float sc = g_scale[o], sh = g_shift[o];
    float r[4] = {v.x, v.y, v.z, v.w};
    #pragma unroll
    for (int i = 0; i < 4; i++) {
        float u = r[i] * sc + sh;
        r[i] = 0.5f * u * (1.f + erff(u * 0.70710678118654752f));
    }
    float4 ov = {r[0], r[1], r[2], r[3]};
    *(float4*)(out + (size_t)b * (COUT * NTOK) + (size_t)o * NTOK + n) = ov;
}

// =====================================================================
extern "C" void kernel_launch(void* const* d_in, const int* in_sizes, int n_in,
                              void* d_out, int out_size)
{
    const float* x     = (const float*)d_in[0];
    const float* w     = (const float*)d_in[1];
    const float* bias  = (const float*)d_in[2];
    const float* gamma = (const float*)d_in[3];
    const float* beta  = (const float*)d_in[4];
    float* out = (float*)d_out;

    cudaFuncSetAttribute(attn_mma_kernel, cudaFuncAttributeMaxDynamicSharedMemorySize, ATT_SMEM_BYTES);
    cudaFuncSetAttribute(conv_kernel,     cudaFuncAttributeMaxDynamicSharedMemorySize, CONV_SMEM_BYTES);

    prep_kernel<<<dim3(NPAD / 64, BATCH), 256>>>(x);
    maxn_kernel<<<BATCH, 256>>>();
    attn_mma_kernel<<<dim3(NQT, BATCH), 256, ATT_SMEM_BYTES>>>(x);
    conv_kernel<<<dim3(NPOS / 256, 2), 256, CONV_SMEM_BYTES>>>(x, w, bias);
    stats_kernel<<<COUT, 256>>>(gamma, beta);
    bngelu_kernel<<<(COUT * NPOS) / 4 / 256, 256>>>(out);
}

// round 13
// speedup vs baseline: 2.2953x; 1.1473x over previous
#include <cuda_runtime.h>
#include <cuda_bf16.h>
#include <math.h>
#include <stdint.h>

// ---------------- problem constants ----------------
#define BATCH   8
#define CH      96
#define NTOK    3136
#define NPAD    3328          // 13 * 256
#define COUT    192
#define NPOS    (BATCH * NTOK)

#define MQT     256           // queries per CTA
#define NQT     13            // ceil(3136/256)
#define KT      64            // keys per tile
#define NKT     49

// smem layout in bf16 elements; strides conflict-free for ldmatrix
#define QSTR 104
#define KSTR 104
#define VSTR 72
#define SQH  0
#define SQL  (MQT * QSTR)                  // 26624
#define KV0  (SQL + MQT * QSTR)            // 53248
#define KPART (KT * KSTR)                  // 6656
#define VPART (CH * VSTR)                  // 6912
#define BUFSZ (2 * KPART + 2 * VPART)      // 27136
#define SM_ELEMS (KV0 + 2 * BUFSZ)         // 107520
#define ATT_SMEM_BYTES (SM_ELEMS * 2)      // 215040

// ---------------- scratch globals ----------------
__device__ __nv_bfloat16 g_th[BATCH * NPAD * CH];   // token-major hi [b][n][c]
__device__ __nv_bfloat16 g_tl[BATCH * NPAD * CH];   // token-major lo
__device__ __nv_bfloat16 g_chm[BATCH * CH * NTOK];  // channel-major hi [b][c][n]
__device__ __nv_bfloat16 g_clm[BATCH * CH * NTOK];  // channel-major lo
__device__ float g_norm[BATCH * NPAD];
__device__ float g_maxn[BATCH];
__device__ float g_xj[BATCH * CH * NTOK];
__device__ float g_y [COUT * NPOS];
#define NCONVBLK 784
__device__ float g_p1[NCONVBLK * COUT];
__device__ float g_p2[NCONVBLK * COUT];
__device__ float g_scale[COUT];
__device__ float g_shift[COUT];

// ---------------- warp MMA / async-copy helpers (sm_80+ baseline PTX) ----
__device__ __forceinline__ uint32_t smem_u32(const void* p) {
    uint32_t a;
    asm("{ .reg .u64 t; cvta.to.shared.u64 t, %1; cvt.u32.u64 %0, t; }" : "=r"(a) : "l"(p));
    return a;
}
__device__ __forceinline__ void ldmat4(uint32_t* r, uint32_t addr) {
    asm volatile("ldmatrix.sync.aligned.m8n8.x4.shared.b16 {%0,%1,%2,%3}, [%4];"
        : "=r"(r[0]), "=r"(r[1]), "=r"(r[2]), "=r"(r[3]) : "r"(addr));
}
__device__ __forceinline__ void mma_bf16(float* d, const uint32_t* a, const uint32_t* b) {
    asm volatile("mma.sync.aligned.m16n8k16.row.col.f32.bf16.bf16.f32 "
        "{%0,%1,%2,%3}, {%4,%5,%6,%7}, {%8,%9}, {%0,%1,%2,%3};"
        : "+f"(d[0]), "+f"(d[1]), "+f"(d[2]), "+f"(d[3])
        : "r"(a[0]), "r"(a[1]), "r"(a[2]), "r"(a[3]), "r"(b[0]), "r"(b[1]));
}
#define CPA16(dst, src) asm volatile("cp.async.cg.shared.global [%0], [%1], 16;" :: "r"(dst), "l"(src) : "memory")
#define CPA_COMMIT()    asm volatile("cp.async.commit_group;" ::: "memory")
#define CPA_WAIT1()     asm volatile("cp.async.wait_group 1;" ::: "memory")
#define CPA_WAIT0()     asm volatile("cp.async.wait_group 0;" ::: "memory")

// =====================================================================
// prep: bf16 hi/lo split in token-major + channel-major layouts, norms
// grid (NPAD/64, 8), 256 threads, each block 64 tokens x 96 ch
// =====================================================================
__global__ void __launch_bounds__(256) prep_kernel(const float* __restrict__ x)
{
    __shared__ float tile[CH][65];
    const int b = blockIdx.y;
    const int n0 = blockIdx.x * 64;
    const int tid = threadIdx.x;
    const bool valid = (n0 < NTOK);
    const float* xb = x + (size_t)b * CH * NTOK;

    for (int i = tid; i < CH * 16; i += 256) {
        int c = i >> 4;
        int q4 = (i & 15) << 2;
        float4 v = make_float4(0.f, 0.f, 0.f, 0.f);
        if (valid) v = *(const float4*)(xb + (size_t)c * NTOK + n0 + q4);
        tile[c][q4+0] = v.x; tile[c][q4+1] = v.y; tile[c][q4+2] = v.z; tile[c][q4+3] = v.w;
        if (valid) {
            uint32_t h0, h1, l0, l1;
            asm("cvt.rn.bf16x2.f32 %0, %1, %2;" : "=r"(h0) : "f"(v.y), "f"(v.x));
            asm("cvt.rn.bf16x2.f32 %0, %1, %2;" : "=r"(h1) : "f"(v.w), "f"(v.z));
            float r0 = v.x - __uint_as_float(h0 << 16);
            float r1 = v.y - __uint_as_float(h0 & 0xffff0000u);
            float r2 = v.z - __uint_as_float(h1 << 16);
            float r3 = v.w - __uint_as_float(h1 & 0xffff0000u);
            asm("cvt.rn.bf16x2.f32 %0, %1, %2;" : "=r"(l0) : "f"(r1), "f"(r0));
            asm("cvt.rn.bf16x2.f32 %0, %1, %2;" : "=r"(l1) : "f"(r3), "f"(r2));
            size_t gi = ((size_t)b * CH + c) * NTOK + n0 + q4;
            *(uint2*)(g_chm + gi) = make_uint2(h0, h1);
            *(uint2*)(g_clm + gi) = make_uint2(l0, l1);
        }
    }
    __syncthreads();
    for (int i = tid; i < 64 * 12; i += 256) {
        int tt = i / 12, u = i - tt * 12;
        int c0 = u * 8;
        uint32_t h[4], lo[4];
        #pragma unroll
        for (int k = 0; k < 4; k++) {
            float a  = tile[c0 + 2*k][tt];
            float bb = tile[c0 + 2*k + 1][tt];
            asm("cvt.rn.bf16x2.f32 %0, %1, %2;" : "=r"(h[k]) : "f"(bb), "f"(a));
            float ra = a  - __uint_as_float(h[k] << 16);
            float rb = bb - __uint_as_float(h[k] & 0xffff0000u);
            asm("cvt.rn.bf16x2.f32 %0, %1, %2;" : "=r"(lo[k]) : "f"(rb), "f"(ra));
        }
        size_t gi = ((size_t)b * NPAD + n0 + tt) * CH + c0;
        *(uint4*)(g_th + gi) = make_uint4(h[0], h[1], h[2], h[3]);
        *(uint4*)(g_tl + gi) = make_uint4(lo[0], lo[1], lo[2], lo[3]);
    }
    if (tid < 64) {
        float s = 0.f;
        #pragma unroll
        for (int c = 0; c < CH; c++) { float v = tile[c][tid]; s += v * v; }
        g_norm[b * NPAD + n0 + tid] = sqrtf(s);
    }
}

__global__ void __launch_bounds__(256) maxn_kernel()
{
    const int b = blockIdx.x, tid = threadIdx.x;
    __shared__ float red[256];
    float m = 0.f;
    for (int i = tid; i < NPAD; i += 256) m = fmaxf(m, g_norm[b * NPAD + i]);
    red[tid] = m; __syncthreads();
    for (int d = 128; d > 0; d >>= 1) { if (tid < d) red[tid] = fmaxf(red[tid], red[tid + d]); __syncthreads(); }
    if (tid == 0) g_maxn[b] = red[0];
}

// =====================================================================
// attention: mma.sync bf16 split-hi/lo, static-bound softmax, O in regs
// cp.async double-buffered K/V. grid (13, 8), 512 threads (16 warps)
// single wave (104 CTAs), 4 warps/SMSP for latency hiding
// =====================================================================
__global__ void __launch_bounds__(512)
attn_mma_kernel(const float* __restrict__ x)
{
    extern __shared__ __nv_bfloat16 sm[];
    const uint32_t sb = smem_u32(sm);
    const int tid  = threadIdx.x;
    const int wid  = tid >> 5;          // 0..15
    const int lane = tid & 31;
    const int g    = lane >> 2;
    const int tig  = lane & 3;
    const int b    = blockIdx.y;
    const int n0   = blockIdx.x * MQT;

    // ---- load Q tile (hi/lo) 256 x 96 (plain stores)
    for (int i = tid; i < MQT * 12; i += 512) {
        int r = i / 12, u = i - r * 12;
        size_t src = ((size_t)(b * NPAD + n0 + r)) * CH + u * 8;
        *(uint4*)(sm + SQH + r * QSTR + u * 8) = *(const uint4*)(g_th + src);
        *(uint4*)(sm + SQL + r * QSTR + u * 8) = *(const uint4*)(g_tl + src);
    }

    // ---- async prefetch of KV tile t into buffer d
    auto issue_kv = [&](int t, int d) {
        const int koff = KV0 + d * BUFSZ;
        const int voff = koff + 2 * KPART;
        const size_t ksrc = ((size_t)(b * NPAD + t * KT)) * CH;
        for (int i = tid; i < KT * 12; i += 512) {
            int r = i / 12, u = i - r * 12;
            uint32_t dst = sb + 2u * (uint32_t)(koff + r * KSTR + u * 8);
            CPA16(dst,              (const void*)(g_th + ksrc + r * CH + u * 8));
            CPA16(dst + 2u * KPART, (const void*)(g_tl + ksrc + r * CH + u * 8));
        }
        const size_t vsrc = (size_t)b * CH * NTOK + (size_t)t * KT;
        for (int i = tid; i < CH * 8; i += 512) {
            int c = i >> 3, u = i & 7;
            uint32_t dst = sb + 2u * (uint32_t)(voff + c * VSTR + u * 8);
            CPA16(dst,              (const void*)(g_chm + vsrc + (size_t)c * NTOK + u * 8));
            CPA16(dst + 2u * VPART, (const void*)(g_clm + vsrc + (size_t)c * NTOK + u * 8));
        }
    };

    issue_kv(0, 0);
    CPA_COMMIT();

    const float maxn = g_maxn[b];
    const float E0 = g_norm[b * NPAD + n0 + wid * 16 + g]     * maxn;
    const float E1 = g_norm[b * NPAD + n0 + wid * 16 + g + 8] * maxn;

    float o[12][4];
    #pragma unroll
    for (int j = 0; j < 12; j++)
        #pragma unroll
        for (int q = 0; q < 4; q++) o[j][q] = 0.f;
    float l0 = 0.f, l1 = 0.f;

    const int l16 = lane & 15;
    const int hf8 = (lane >> 4) * 8;
    const uint32_t qbase = sb + 2u * (uint32_t)(SQH + (wid * 16 + l16) * QSTR + hf8);
    const uint32_t qlo   = 2u * (uint32_t)(SQL - SQH);
    const uint32_t klo   = 2u * (uint32_t)KPART;
    const uint32_t vlo   = 2u * (uint32_t)VPART;

    for (int t = 0; t < NKT; t++) {
        if (t + 1 < NKT) {
            issue_kv(t + 1, (t + 1) & 1);
            CPA_COMMIT();
            CPA_WAIT1();
        } else {
            CPA_WAIT0();
        }
        __syncthreads();

        const int koff = KV0 + (t & 1) * BUFSZ;
        const uint32_t kbase = sb + 2u * (uint32_t)(koff + l16 * KSTR + hf8);
        const uint32_t vbase = sb + 2u * (uint32_t)(koff + 2 * KPART + l16 * VSTR + hf8);

        // ---- S = Q K^T (16 x 64 per warp), 3-term split
        float s[8][4];
        #pragma unroll
        for (int j = 0; j < 8; j++)
            #pragma unroll
            for (int q = 0; q < 4; q++) s[j][q] = 0.f;

        #pragma unroll
        for (int kb = 0; kb < 6; kb++) {
            uint32_t qh[4], ql[4];
            ldmat4(qh, qbase + kb * 32);
            ldmat4(ql, qbase + qlo + kb * 32);
            #pragma unroll
            for (int nb = 0; nb < 4; nb++) {
                uint32_t bh[4], blr[4];
                uint32_t ka = kbase + (uint32_t)(nb * 16 * KSTR * 2) + kb * 32;
                ldmat4(bh, ka);
                ldmat4(blr, ka + klo);
                uint32_t b0[2] = {bh[0], bh[2]},  b1[2] = {bh[1], bh[3]};
                uint32_t c0[2] = {blr[0], blr[2]}, c1[2] = {blr[1], blr[3]};
                mma_bf16(s[2*nb],   qh, b0);
                mma_bf16(s[2*nb+1], qh, b1);
                mma_bf16(s[2*nb],   qh, c0);
                mma_bf16(s[2*nb+1], qh, c1);
                mma_bf16(s[2*nb],   ql, b0);
                mma_bf16(s[2*nb+1], ql, b1);
            }
        }

        // ---- softmax p = exp(s - E); pack P hi/lo A-fragments in registers
        uint32_t pha[4][4], pla[4][4];
        #pragma unroll
        for (int j = 0; j < 8; j++) {
            float p0 = __expf(s[j][0] - E0);
            float p1 = __expf(s[j][1] - E0);
            float p2 = __expf(s[j][2] - E1);
            float p3 = __expf(s[j][3] - E1);
            l0 += p0 + p1; l1 += p2 + p3;
            uint32_t h01, h23, q01, q23;
            asm("cvt.rn.bf16x2.f32 %0, %1, %2;" : "=r"(h01) : "f"(p1), "f"(p0));
            asm("cvt.rn.bf16x2.f32 %0, %1, %2;" : "=r"(h23) : "f"(p3), "f"(p2));
            float r0 = p0 - __uint_as_float(h01 << 16);
            float r1 = p1 - __uint_as_float(h01 & 0xffff0000u);
            float r2 = p2 - __uint_as_float(h23 << 16);
            float r3 = p3 - __uint_as_float(h23 & 0xffff0000u);
            asm("cvt.rn.bf16x2.f32 %0, %1, %2;" : "=r"(q01) : "f"(r1), "f"(r0));
            asm("cvt.rn.bf16x2.f32 %0, %1, %2;" : "=r"(q23) : "f"(r3), "f"(r2));
            int kb = j >> 1;
            if ((j & 1) == 0) { pha[kb][0] = h01; pha[kb][1] = h23; pla[kb][0] = q01; pla[kb][1] = q23; }
            else              { pha[kb][2] = h01; pha[kb][3] = h23; pla[kb][2] = q01; pla[kb][3] = q23; }
        }

        // ---- O += P V (16 x 96 per warp), 3-term split
        #pragma unroll
        for (int kb = 0; kb < 4; kb++) {
            #pragma unroll
            for (int vb = 0; vb < 6; vb++) {
                uint32_t vh[4], vl[4];
                uint32_t va = vbase + (uint32_t)(vb * 16 * VSTR * 2) + kb * 32;
                ldmat4(vh, va);
                ldmat4(vl, va + vlo);
                uint32_t b0[2] = {vh[0], vh[2]}, b1[2] = {vh[1], vh[3]};
                uint32_t c0[2] = {vl[0], vl[2]}, c1[2] = {vl[1], vl[3]};
                mma_bf16(o[2*vb],   pha[kb], b0);
                mma_bf16(o[2*vb+1], pha[kb], b1);
                mma_bf16(o[2*vb],   pha[kb], c0);
                mma_bf16(o[2*vb+1], pha[kb], c1);
                mma_bf16(o[2*vb],   pla[kb], b0);
                mma_bf16(o[2*vb+1], pla[kb], b1);
            }
        }
        __syncthreads();
    }

    // ---- row sums across the quad
    l0 += __shfl_xor_sync(0xffffffffu, l0, 1);
    l0 += __shfl_xor_sync(0xffffffffu, l0, 2);
    l1 += __shfl_xor_sync(0xffffffffu, l1, 1);
    l1 += __shfl_xor_sync(0xffffffffu, l1, 2);
    const float i0 = 1.f / l0, i1 = 1.f / l1;

    float* stage = (float*)sm;   // 256 x 100 floats, reuses Q region (102.4KB <= 106.5KB)
    #pragma unroll
    for (int j = 0; j < 12; j++) {
        int c = 8 * j + 2 * tig;
        stage[(wid * 16 + g) * 100 + c]         = o[j][0] * i0;
        stage[(wid * 16 + g) * 100 + c + 1]     = o[j][1] * i0;
        stage[(wid * 16 + g + 8) * 100 + c]     = o[j][2] * i1;
        stage[(wid * 16 + g + 8) * 100 + c + 1] = o[j][3] * i1;
    }
    __syncthreads();

    const float* xb = x + (size_t)b * CH * NTOK;
    for (int i = tid; i < CH * 64; i += 512) {
        int c = i >> 6, q4 = (i & 63) << 2;
        int n = n0 + q4;
        if (n < NTOK) {
            float4 xv = *(const float4*)(xb + (size_t)c * NTOK + n);
            float4 ov;
            ov.x = fmaxf(xv.x - stage[(q4 + 0) * 100 + c], 0.f);
            ov.y = fmaxf(xv.y - stage[(q4 + 1) * 100 + c], 0.f);
            ov.z = fmaxf(xv.z - stage[(q4 + 2) * 100 + c], 0.f);
            ov.w = fmaxf(xv.w - stage[(q4 + 3) * 100 + c], 0.f);
            *(float4*)(g_xj + ((size_t)b * CH + c) * NTOK + n) = ov;
        }
    }
}

// =====================================================================
// conv: grid (98, 2), 192 threads, occ 2 -> single wave of 196 CTAs.
// W transposed in smem (Wt[k][o], float4 loads), cs stride 36 (float4).
// Each thread: 4 outputs x 4 positions = 16 FFMA per 2 LDS.128.
// =====================================================================
#define WTILE 96
#define WTSTR 100
#define CSTR  36
#define CONV_SMEM_FLOATS ((2*CH) * WTSTR + (2*CH) * CSTR)
#define CONV_SMEM_BYTES  (CONV_SMEM_FLOATS * 4)

__global__ void __launch_bounds__(192, 2)
conv_kernel(const float* __restrict__ x, const float* __restrict__ w,
            const float* __restrict__ bias)
{
    extern __shared__ float smf[];
    float* Wt = smf;                       // [192 k][100] (96 outs used)
    float* cs = smf + (2*CH) * WTSTR;      // [192 k][36]  (32 pos used)

    const int tid = threadIdx.x;
    const int oh  = blockIdx.y;
    const int obase = oh * WTILE;

    // load W transposed: coalesced over k
    for (int i = tid; i < WTILE * (2 * CH); i += 192) {
        int o = i / (2 * CH), k = i - o * (2 * CH);
        Wt[k * WTSTR + o] = w[(obase + o) * (2 * CH) + k];
    }

    const int og = tid / 8;     // 0..23, owns outputs og*4..og*4+3
    const int pg = tid & 7;     // 0..7,  owns positions pg*4..pg*4+3

    for (int chunk = 0; chunk < 8; chunk++) {
        const int p0 = blockIdx.x * 256 + chunk * 32;
        const int b  = p0 / NTOK;
        const int n0 = p0 - b * NTOK;

        __syncthreads();
        for (int i = tid; i < (2 * CH) * 8; i += 192) {
            int k = i >> 3, u = i & 7;
            const float* src = (k < CH)
                ? (x   + ((size_t)b * CH + k) * NTOK + n0 + u * 4)
                : (g_xj + ((size_t)b * CH + (k - CH)) * NTOK + n0 + u * 4);
            *(float4*)(cs + k * CSTR + u * 4) = *(const float4*)src;
        }
        __syncthreads();

        float acc[4][4];
        #pragma unroll
        for (int j = 0; j < 4; j++)
            #pragma unroll
            for (int q = 0; q < 4; q++) acc[j][q] = 0.f;

        for (int k = 0; k < 2 * CH; k++) {
            float4 wv = *(const float4*)(Wt + k * WTSTR + og * 4);
            float4 cv = *(const float4*)(cs + k * CSTR + pg * 4);
            const float* wp = &wv.x;
            const float* cp = &cv.x;
            #pragma unroll
            for (int j = 0; j < 4; j++)
                #pragma unroll
                for (int q = 0; q < 4; q++) acc[j][q] += wp[j] * cp[q];
        }

        const int pb = blockIdx.x * 8 + chunk;
        #pragma unroll
        for (int j = 0; j < 4; j++) {
            const int o = obase + og * 4 + j;
            const float bi = bias[o];
            float a1 = 0.f, a2 = 0.f;
            #pragma unroll
            for (int q = 0; q < 4; q++) {
                float y = acc[j][q] + bi;
                g_y[(size_t)o * NPOS + p0 + pg * 4 + q] = y;
                a1 += y;
                a2 += y * y;
            }
            #pragma unroll
            for (int d = 4; d > 0; d >>= 1) {
                a1 += __shfl_down_sync(0xffffffffu, a1, d, 8);
                a2 += __shfl_down_sync(0xffffffffu, a2, d, 8);
            }
            if (pg == 0) {
                g_p1[pb * COUT + o] = a1;
                g_p2[pb * COUT + o] = a2;
            }
        }
    }
}

__global__ void __launch_bounds__(256)
stats_kernel(const float* __restrict__ gamma, const float* __restrict__ beta)
{
    const int o = blockIdx.x;
    const int tid = threadIdx.x;
    float s1 = 0.f, s2 = 0.f;
    for (int i = tid; i < NCONVBLK; i += 256) {
        s1 += g_p1[i * COUT + o];
        s2 += g_p2[i * COUT + o];
    }
    __shared__ float r1[256], r2[256];
    r1[tid] = s1; r2[tid] = s2;
    __syncthreads();
    for (int d = 128; d > 0; d >>= 1) {
        if (tid < d) { r1[tid] += r1[tid + d]; r2[tid] += r2[tid + d]; }
        __syncthreads();
    }
    if (tid == 0) {
        const float invN = 1.f / (float)NPOS;
        float mean = r1[0] * invN;
        float var  = r2[0] * invN - mean * mean;
        float rstd = rsqrtf(var + 1e-5f);
        float gg = gamma[o] * rstd;
        g_scale[o] = gg;
        g_shift[o] = beta[o] - mean * gg;
    }
}

__global__ void __launch_bounds__(256)
bngelu_kernel(float* __restrict__ out)
{
    const int idx4 = blockIdx.x * 256 + threadIdx.x;
    const int base = idx4 * 4;
    const int o = base / NPOS;
    const int p = base - o * NPOS;
    const int b = p / NTOK;
    const int n = p - b * NTOK;

    float4 v = *(const float4*)(g_y + base);
    const float sc = g_scale[o], sh = g_shift[o];
    float r[4] = {v.x, v.y, v.z, v.w};
    #pragma unroll
    for (int i = 0; i < 4; i++) {
        float u = r[i] * sc + sh;
        r[i] = 0.5f * u * (1.f + erff(u * 0.70710678118654752f));
    }
    float4 ov = {r[0], r[1], r[2], r[3]};
    *(float4*)(out + (size_t)b * (COUT * NTOK) + (size_t)o * NTOK + n) = ov;
}

// =====================================================================
extern "C" void kernel_launch(void* const* d_in, const int* in_sizes, int n_in,
                              void* d_out, int out_size)
{
    const float* x     = (const float*)d_in[0];
    const float* w     = (const float*)d_in[1];
    const float* bias  = (const float*)d_in[2];
    const float* gamma = (const float*)d_in[3];
    const float* beta  = (const float*)d_in[4];
    float* out = (float*)d_out;

    cudaFuncSetAttribute(attn_mma_kernel, cudaFuncAttributeMaxDynamicSharedMemorySize, ATT_SMEM_BYTES);
    cudaFuncSetAttribute(conv_kernel,     cudaFuncAttributeMaxDynamicSharedMemorySize, CONV_SMEM_BYTES);

    prep_kernel<<<dim3(NPAD / 64, BATCH), 256>>>(x);
    maxn_kernel<<<BATCH, 256>>>();
    attn_mma_kernel<<<dim3(NQT, BATCH), 512, ATT_SMEM_BYTES>>>(x);
    conv_kernel<<<dim3(NPOS / 256, 2), 192, CONV_SMEM_BYTES>>>(x, w, bias);
    stats_kernel<<<COUT, 256>>>(gamma, beta);
    bngelu_kernel<<<(COUT * NPOS) / 4 / 256, 256>>>(out);
}

// round 16
// speedup vs baseline: 2.3987x; 1.0450x over previous
#include <cuda_runtime.h>
#include <cuda_bf16.h>
#include <math.h>
#include <stdint.h>

// ---------------- problem constants ----------------
#define BATCH   8
#define CH      96
#define NTOK    3136
#define NPAD    3328          // 13 * 256
#define COUT    192
#define NPOS    (BATCH * NTOK)

#define MQT     256           // queries per CTA
#define NQT     13
#define KT      64            // keys per tile
#define NKT     49

// smem layout in bf16 elements; strides conflict-free for ldmatrix
#define QSTR 104
#define KSTR 104
#define VSTR 72
#define SQH  0
#define SQL  (MQT * QSTR)                  // 26624
#define KV0  (SQL + MQT * QSTR)            // 53248
#define KPART (KT * KSTR)                  // 6656
#define VPART (CH * VSTR)                  // 6912
#define BUFSZ (2 * KPART + 2 * VPART)      // 27136
#define SM_ELEMS (KV0 + 2 * BUFSZ)         // 107520
#define ATT_SMEM_BYTES (SM_ELEMS * 2)      // 215040

// ---------------- scratch globals ----------------
__device__ __nv_bfloat16 g_th[BATCH * NPAD * CH];   // token-major hi [b][n][c]
__device__ __nv_bfloat16 g_tl[BATCH * NPAD * CH];   // token-major lo
__device__ __nv_bfloat16 g_chm[BATCH * CH * NTOK];  // channel-major hi [b][c][n]
__device__ __nv_bfloat16 g_clm[BATCH * CH * NTOK];  // channel-major lo
__device__ float g_norm[BATCH * NPAD];
__device__ float g_maxn[BATCH];
__device__ float g_xj[BATCH * CH * NTOK];
__device__ float g_y [COUT * NPOS];
#define NCONVBLK 784
__device__ float g_p1[NCONVBLK * COUT];
__device__ float g_p2[NCONVBLK * COUT];
__device__ float g_scale[COUT];
__device__ float g_shift[COUT];

// ---------------- warp MMA / async-copy helpers (sm_80+ baseline PTX) ----
__device__ __forceinline__ uint32_t smem_u32(const void* p) {
    uint32_t a;
    asm("{ .reg .u64 t; cvta.to.shared.u64 t, %1; cvt.u32.u64 %0, t; }" : "=r"(a) : "l"(p));
    return a;
}
__device__ __forceinline__ void ldmat4(uint32_t* r, uint32_t addr) {
    asm volatile("ldmatrix.sync.aligned.m8n8.x4.shared.b16 {%0,%1,%2,%3}, [%4];"
        : "=r"(r[0]), "=r"(r[1]), "=r"(r[2]), "=r"(r[3]) : "r"(addr));
}
__device__ __forceinline__ void mma_bf16(float* d, const uint32_t* a, const uint32_t* b) {
    asm volatile("mma.sync.aligned.m16n8k16.row.col.f32.bf16.bf16.f32 "
        "{%0,%1,%2,%3}, {%4,%5,%6,%7}, {%8,%9}, {%0,%1,%2,%3};"
        : "+f"(d[0]), "+f"(d[1]), "+f"(d[2]), "+f"(d[3])
        : "r"(a[0]), "r"(a[1]), "r"(a[2]), "r"(a[3]), "r"(b[0]), "r"(b[1]));
}
#define CPA16(dst, src) asm volatile("cp.async.cg.shared.global [%0], [%1], 16;" :: "r"(dst), "l"(src) : "memory")
#define CPA_COMMIT()    asm volatile("cp.async.commit_group;" ::: "memory")
#define CPA_WAIT1()     asm volatile("cp.async.wait_group 1;" ::: "memory")
#define CPA_WAIT0()     asm volatile("cp.async.wait_group 0;" ::: "memory")

// =====================================================================
// prep: bf16 hi/lo split in token-major + channel-major layouts, norms
// =====================================================================
__global__ void __launch_bounds__(256) prep_kernel(const float* __restrict__ x)
{
    __shared__ float tile[CH][65];
    const int b = blockIdx.y;
    const int n0 = blockIdx.x * 64;
    const int tid = threadIdx.x;
    const bool valid = (n0 < NTOK);
    const float* xb = x + (size_t)b * CH * NTOK;

    for (int i = tid; i < CH * 16; i += 256) {
        int c = i >> 4;
        int q4 = (i & 15) << 2;
        float4 v = make_float4(0.f, 0.f, 0.f, 0.f);
        if (valid) v = *(const float4*)(xb + (size_t)c * NTOK + n0 + q4);
        tile[c][q4+0] = v.x; tile[c][q4+1] = v.y; tile[c][q4+2] = v.z; tile[c][q4+3] = v.w;
        if (valid) {
            uint32_t h0, h1, l0, l1;
            asm("cvt.rn.bf16x2.f32 %0, %1, %2;" : "=r"(h0) : "f"(v.y), "f"(v.x));
            asm("cvt.rn.bf16x2.f32 %0, %1, %2;" : "=r"(h1) : "f"(v.w), "f"(v.z));
            float r0 = v.x - __uint_as_float(h0 << 16);
            float r1 = v.y - __uint_as_float(h0 & 0xffff0000u);
            float r2 = v.z - __uint_as_float(h1 << 16);
            float r3 = v.w - __uint_as_float(h1 & 0xffff0000u);
            asm("cvt.rn.bf16x2.f32 %0, %1, %2;" : "=r"(l0) : "f"(r1), "f"(r0));
            asm("cvt.rn.bf16x2.f32 %0, %1, %2;" : "=r"(l1) : "f"(r3), "f"(r2));
            size_t gi = ((size_t)b * CH + c) * NTOK + n0 + q4;
            *(uint2*)(g_chm + gi) = make_uint2(h0, h1);
            *(uint2*)(g_clm + gi) = make_uint2(l0, l1);
        }
    }
    __syncthreads();
    for (int i = tid; i < 64 * 12; i += 256) {
        int tt = i / 12, u = i - tt * 12;
        int c0 = u * 8;
        uint32_t h[4], lo[4];
        #pragma unroll
        for (int k = 0; k < 4; k++) {
            float a  = tile[c0 + 2*k][tt];
            float bb = tile[c0 + 2*k + 1][tt];
            asm("cvt.rn.bf16x2.f32 %0, %1, %2;" : "=r"(h[k]) : "f"(bb), "f"(a));
            float ra = a  - __uint_as_float(h[k] << 16);
            float rb = bb - __uint_as_float(h[k] & 0xffff0000u);
            asm("cvt.rn.bf16x2.f32 %0, %1, %2;" : "=r"(lo[k]) : "f"(rb), "f"(ra));
        }
        size_t gi = ((size_t)b * NPAD + n0 + tt) * CH + c0;
        *(uint4*)(g_th + gi) = make_uint4(h[0], h[1], h[2], h[3]);
        *(uint4*)(g_tl + gi) = make_uint4(lo[0], lo[1], lo[2], lo[3]);
    }
    if (tid < 64) {
        float s = 0.f;
        #pragma unroll
        for (int c = 0; c < CH; c++) { float v = tile[c][tid]; s += v * v; }
        g_norm[b * NPAD + n0 + tid] = sqrtf(s);
    }
}

__global__ void __launch_bounds__(256) maxn_kernel()
{
    const int b = blockIdx.x, tid = threadIdx.x;
    __shared__ float red[256];
    float m = 0.f;
    for (int i = tid; i < NPAD; i += 256) m = fmaxf(m, g_norm[b * NPAD + i]);
    red[tid] = m; __syncthreads();
    for (int d = 128; d > 0; d >>= 1) { if (tid < d) red[tid] = fmaxf(red[tid], red[tid + d]); __syncthreads(); }
    if (tid == 0) g_maxn[b] = red[0];
}

// =====================================================================
// attention: mma.sync bf16 split-hi/lo, static-bound softmax, O in regs
// M=32 per warp (8 warps, 256 thr) -> halved K/V ldmatrix traffic
// grid (13, 8) = 104 CTAs, single wave
// =====================================================================
__global__ void __launch_bounds__(256)
attn_mma_kernel(const float* __restrict__ x)
{
    extern __shared__ __nv_bfloat16 sm[];
    const uint32_t sb = smem_u32(sm);
    const int tid  = threadIdx.x;
    const int wid  = tid >> 5;          // 0..7
    const int lane = tid & 31;
    const int g    = lane >> 2;
    const int tig  = lane & 3;
    const int b    = blockIdx.y;
    const int n0   = blockIdx.x * MQT;

    // ---- load Q tile (hi/lo) 256 x 96 (plain stores)
    for (int i = tid; i < MQT * 12; i += 256) {
        int r = i / 12, u = i - r * 12;
        size_t src = ((size_t)(b * NPAD + n0 + r)) * CH + u * 8;
        *(uint4*)(sm + SQH + r * QSTR + u * 8) = *(const uint4*)(g_th + src);
        *(uint4*)(sm + SQL + r * QSTR + u * 8) = *(const uint4*)(g_tl + src);
    }

    auto issue_kv = [&](int t, int d) {
        const int koff = KV0 + d * BUFSZ;
        const int voff = koff + 2 * KPART;
        const size_t ksrc = ((size_t)(b * NPAD + t * KT)) * CH;
        for (int i = tid; i < KT * 12; i += 256) {
            int r = i / 12, u = i - r * 12;
            uint32_t dst = sb + 2u * (uint32_t)(koff + r * KSTR + u * 8);
            CPA16(dst,              (const void*)(g_th + ksrc + r * CH + u * 8));
            CPA16(dst + 2u * KPART, (const void*)(g_tl + ksrc + r * CH + u * 8));
        }
        const size_t vsrc = (size_t)b * CH * NTOK + (size_t)t * KT;
        for (int i = tid; i < CH * 8; i += 256) {
            int c = i >> 3, u = i & 7;
            uint32_t dst = sb + 2u * (uint32_t)(voff + c * VSTR + u * 8);
            CPA16(dst,              (const void*)(g_chm + vsrc + (size_t)c * NTOK + u * 8));
            CPA16(dst + 2u * VPART, (const void*)(g_clm + vsrc + (size_t)c * NTOK + u * 8));
        }
    };

    issue_kv(0, 0);
    CPA_COMMIT();

    const float maxn = g_maxn[b];
    float E[2][2];
    #pragma unroll
    for (int mh = 0; mh < 2; mh++) {
        E[mh][0] = g_norm[b * NPAD + n0 + wid * 32 + mh * 16 + g]     * maxn;
        E[mh][1] = g_norm[b * NPAD + n0 + wid * 32 + mh * 16 + g + 8] * maxn;
    }

    float o[2][12][4];
    #pragma unroll
    for (int mh = 0; mh < 2; mh++)
        #pragma unroll
        for (int j = 0; j < 12; j++)
            #pragma unroll
            for (int q = 0; q < 4; q++) o[mh][j][q] = 0.f;
    float lsum[2][2] = {{0.f, 0.f}, {0.f, 0.f}};

    const int l16 = lane & 15;
    const int hf8 = (lane >> 4) * 8;
    uint32_t qbase[2];
    #pragma unroll
    for (int mh = 0; mh < 2; mh++)
        qbase[mh] = sb + 2u * (uint32_t)(SQH + (wid * 32 + mh * 16 + l16) * QSTR + hf8);
    const uint32_t qlo = 2u * (uint32_t)(SQL - SQH);
    const uint32_t klo = 2u * (uint32_t)KPART;
    const uint32_t vlo = 2u * (uint32_t)VPART;

    for (int t = 0; t < NKT; t++) {
        if (t + 1 < NKT) {
            issue_kv(t + 1, (t + 1) & 1);
            CPA_COMMIT();
            CPA_WAIT1();
        } else {
            CPA_WAIT0();
        }
        __syncthreads();

        const int koff = KV0 + (t & 1) * BUFSZ;
        const uint32_t kbase = sb + 2u * (uint32_t)(koff + l16 * KSTR + hf8);
        const uint32_t vbase = sb + 2u * (uint32_t)(koff + 2 * KPART + l16 * VSTR + hf8);

        // ---- S = Q K^T (32 x 64 per warp), 3-term split
        float s[2][8][4];
        #pragma unroll
        for (int mh = 0; mh < 2; mh++)
            #pragma unroll
            for (int j = 0; j < 8; j++)
                #pragma unroll
                for (int q = 0; q < 4; q++) s[mh][j][q] = 0.f;

        #pragma unroll
        for (int kb = 0; kb < 6; kb++) {
            uint32_t qh[2][4], ql[2][4];
            #pragma unroll
            for (int mh = 0; mh < 2; mh++) {
                ldmat4(qh[mh], qbase[mh] + kb * 32);
                ldmat4(ql[mh], qbase[mh] + qlo + kb * 32);
            }
            #pragma unroll
            for (int nb = 0; nb < 4; nb++) {
                uint32_t bh[4], blr[4];
                uint32_t ka = kbase + (uint32_t)(nb * 16 * KSTR * 2) + kb * 32;
                ldmat4(bh, ka);
                ldmat4(blr, ka + klo);
                uint32_t b0[2] = {bh[0], bh[2]},  b1[2] = {bh[1], bh[3]};
                uint32_t c0[2] = {blr[0], blr[2]}, c1[2] = {blr[1], blr[3]};
                #pragma unroll
                for (int mh = 0; mh < 2; mh++) {
                    mma_bf16(s[mh][2*nb],   qh[mh], b0);
                    mma_bf16(s[mh][2*nb+1], qh[mh], b1);
                    mma_bf16(s[mh][2*nb],   qh[mh], c0);
                    mma_bf16(s[mh][2*nb+1], qh[mh], c1);
                    mma_bf16(s[mh][2*nb],   ql[mh], b0);
                    mma_bf16(s[mh][2*nb+1], ql[mh], b1);
                }
            }
        }

        // ---- softmax p = exp(s - E); pack P hi/lo A-fragments in registers
        uint32_t pha[2][4][4], pla[2][4][4];
        #pragma unroll
        for (int mh = 0; mh < 2; mh++) {
            #pragma unroll
            for (int j = 0; j < 8; j++) {
                float p0 = __expf(s[mh][j][0] - E[mh][0]);
                float p1 = __expf(s[mh][j][1] - E[mh][0]);
                float p2 = __expf(s[mh][j][2] - E[mh][1]);
                float p3 = __expf(s[mh][j][3] - E[mh][1]);
                lsum[mh][0] += p0 + p1; lsum[mh][1] += p2 + p3;
                uint32_t h01, h23, q01, q23;
                asm("cvt.rn.bf16x2.f32 %0, %1, %2;" : "=r"(h01) : "f"(p1), "f"(p0));
                asm("cvt.rn.bf16x2.f32 %0, %1, %2;" : "=r"(h23) : "f"(p3), "f"(p2));
                float r0 = p0 - __uint_as_float(h01 << 16);
                float r1 = p1 - __uint_as_float(h01 & 0xffff0000u);
                float r2 = p2 - __uint_as_float(h23 << 16);
                float r3 = p3 - __uint_as_float(h23 & 0xffff0000u);
                asm("cvt.rn.bf16x2.f32 %0, %1, %2;" : "=r"(q01) : "f"(r1), "f"(r0));
                asm("cvt.rn.bf16x2.f32 %0, %1, %2;" : "=r"(q23) : "f"(r3), "f"(r2));
                int kb = j >> 1;
                if ((j & 1) == 0) { pha[mh][kb][0] = h01; pha[mh][kb][1] = h23; pla[mh][kb][0] = q01; pla[mh][kb][1] = q23; }
                else              { pha[mh][kb][2] = h01; pha[mh][kb][3] = h23; pla[mh][kb][2] = q01; pla[mh][kb][3] = q23; }
            }
        }

        // ---- O += P V (32 x 96 per warp), 3-term split
        #pragma unroll
        for (int kb = 0; kb < 4; kb++) {
            #pragma unroll
            for (int vb = 0; vb < 6; vb++) {
                uint32_t vh[4], vl[4];
                uint32_t va = vbase + (uint32_t)(vb * 16 * VSTR * 2) + kb * 32;
                ldmat4(vh, va);
                ldmat4(vl, va + vlo);
                uint32_t b0[2] = {vh[0], vh[2]}, b1[2] = {vh[1], vh[3]};
                uint32_t c0[2] = {vl[0], vl[2]}, c1[2] = {vl[1], vl[3]};
                #pragma unroll
                for (int mh = 0; mh < 2; mh++) {
                    mma_bf16(o[mh][2*vb],   pha[mh][kb], b0);
                    mma_bf16(o[mh][2*vb+1], pha[mh][kb], b1);
                    mma_bf16(o[mh][2*vb],   pha[mh][kb], c0);
                    mma_bf16(o[mh][2*vb+1], pha[mh][kb], c1);
                    mma_bf16(o[mh][2*vb],   pla[mh][kb], b0);
                    mma_bf16(o[mh][2*vb+1], pla[mh][kb], b1);
                }
            }
        }
        __syncthreads();
    }

    // ---- row sums across the quad
    #pragma unroll
    for (int mh = 0; mh < 2; mh++) {
        lsum[mh][0] += __shfl_xor_sync(0xffffffffu, lsum[mh][0], 1);
        lsum[mh][0] += __shfl_xor_sync(0xffffffffu, lsum[mh][0], 2);
        lsum[mh][1] += __shfl_xor_sync(0xffffffffu, lsum[mh][1], 1);
        lsum[mh][1] += __shfl_xor_sync(0xffffffffu, lsum[mh][1], 2);
    }

    float* stage = (float*)sm;   // 256 x 100 floats (102.4KB), reuses Q region
    #pragma unroll
    for (int mh = 0; mh < 2; mh++) {
        const float i0 = 1.f / lsum[mh][0], i1 = 1.f / lsum[mh][1];
        const int r0 = wid * 32 + mh * 16 + g;
        #pragma unroll
        for (int j = 0; j < 12; j++) {
            int c = 8 * j + 2 * tig;
            stage[r0 * 100 + c]           = o[mh][j][0] * i0;
            stage[r0 * 100 + c + 1]       = o[mh][j][1] * i0;
            stage[(r0 + 8) * 100 + c]     = o[mh][j][2] * i1;
            stage[(r0 + 8) * 100 + c + 1] = o[mh][j][3] * i1;
        }
    }
    __syncthreads();

    const float* xb = x + (size_t)b * CH * NTOK;
    for (int i = tid; i < CH * 64; i += 256) {
        int c = i >> 6, q4 = (i & 63) << 2;
        int n = n0 + q4;
        if (n < NTOK) {
            float4 xv = *(const float4*)(xb + (size_t)c * NTOK + n);
            float4 ov;
            ov.x = fmaxf(xv.x - stage[(q4 + 0) * 100 + c], 0.f);
            ov.y = fmaxf(xv.y - stage[(q4 + 1) * 100 + c], 0.f);
            ov.z = fmaxf(xv.z - stage[(q4 + 2) * 100 + c], 0.f);
            ov.w = fmaxf(xv.w - stage[(q4 + 3) * 100 + c], 0.f);
            *(float4*)(g_xj + ((size_t)b * CH + c) * NTOK + n) = ov;
        }
    }
}

// =====================================================================
// conv: grid (98, 3), 128 threads, occ 2 -> ~all SMs at 2 CTAs, 1 wave.
// WTILE=64 outs per CTA; W transposed (Wt[k][o], float4), cs float4.
// =====================================================================
#define WTILE 64
#define WTSTR 68
#define CSTR  36
#define CONV_SMEM_FLOATS ((2*CH) * WTSTR + (2*CH) * CSTR)
#define CONV_SMEM_BYTES  (CONV_SMEM_FLOATS * 4)

__global__ void __launch_bounds__(128, 2)
conv_kernel(const float* __restrict__ x, const float* __restrict__ w,
            const float* __restrict__ bias)
{
    extern __shared__ float smf[];
    float* Wt = smf;                       // [192 k][68] (64 outs used)
    float* cs = smf + (2*CH) * WTSTR;      // [192 k][36] (32 pos used)

    const int tid = threadIdx.x;
    const int oh  = blockIdx.y;            // 0..2
    const int obase = oh * WTILE;

    for (int i = tid; i < WTILE * (2 * CH); i += 128) {
        int o = i / (2 * CH), k = i - o * (2 * CH);
        Wt[k * WTSTR + o] = w[(obase + o) * (2 * CH) + k];
    }

    const int og = tid >> 3;    // 0..15, owns outputs og*4..og*4+3
    const int pg = tid & 7;     // 0..7,  owns positions pg*4..pg*4+3

    for (int chunk = 0; chunk < 8; chunk++) {
        const int p0 = blockIdx.x * 256 + chunk * 32;
        const int b  = p0 / NTOK;
        const int n0 = p0 - b * NTOK;

        __syncthreads();
        for (int i = tid; i < (2 * CH) * 8; i += 128) {
            int k = i >> 3, u = i & 7;
            const float* src = (k < CH)
                ? (x    + ((size_t)b * CH + k) * NTOK + n0 + u * 4)
                : (g_xj + ((size_t)b * CH + (k - CH)) * NTOK + n0 + u * 4);
            *(float4*)(cs + k * CSTR + u * 4) = *(const float4*)src;
        }
        __syncthreads();

        float acc[4][4];
        #pragma unroll
        for (int j = 0; j < 4; j++)
            #pragma unroll
            for (int q = 0; q < 4; q++) acc[j][q] = 0.f;

        for (int k = 0; k < 2 * CH; k++) {
            float4 wv = *(const float4*)(Wt + k * WTSTR + og * 4);
            float4 cv = *(const float4*)(cs + k * CSTR + pg * 4);
            const float* wp = &wv.x;
            const float* cp = &cv.x;
            #pragma unroll
            for (int j = 0; j < 4; j++)
                #pragma unroll
                for (int q = 0; q < 4; q++) acc[j][q] += wp[j] * cp[q];
        }

        const int pb = blockIdx.x * 8 + chunk;
        #pragma unroll
        for (int j = 0; j < 4; j++) {
            const int o = obase + og * 4 + j;
            const float bi = bias[o];
            float a1 = 0.f, a2 = 0.f;
            #pragma unroll
            for (int q = 0; q < 4; q++) {
                float y = acc[j][q] + bi;
                g_y[(size_t)o * NPOS + p0 + pg * 4 + q] = y;
                a1 += y;
                a2 += y * y;
            }
            #pragma unroll
            for (int d = 4; d > 0; d >>= 1) {
                a1 += __shfl_down_sync(0xffffffffu, a1, d, 8);
                a2 += __shfl_down_sync(0xffffffffu, a2, d, 8);
            }
            if (pg == 0) {
                g_p1[pb * COUT + o] = a1;
                g_p2[pb * COUT + o] = a2;
            }
        }
    }
}

__global__ void __launch_bounds__(256)
stats_kernel(const float* __restrict__ gamma, const float* __restrict__ beta)
{
    const int o = blockIdx.x;
    const int tid = threadIdx.x;
    float s1 = 0.f, s2 = 0.f;
    for (int i = tid; i < NCONVBLK; i += 256) {
        s1 += g_p1[i * COUT + o];
        s2 += g_p2[i * COUT + o];
    }
    __shared__ float r1[256], r2[256];
    r1[tid] = s1; r2[tid] = s2;
    __syncthreads();
    for (int d = 128; d > 0; d >>= 1) {
        if (tid < d) { r1[tid] += r1[tid + d]; r2[tid] += r2[tid + d]; }
        __syncthreads();
    }
    if (tid == 0) {
        const float invN = 1.f / (float)NPOS;
        float mean = r1[0] * invN;
        float var  = r2[0] * invN - mean * mean;
        float rstd = rsqrtf(var + 1e-5f);
        float gg = gamma[o] * rstd;
        g_scale[o] = gg;
        g_shift[o] = beta[o] - mean * gg;
    }
}

__global__ void __launch_bounds__(256)
bngelu_kernel(float* __restrict__ out)
{
    const int idx4 = blockIdx.x * 256 + threadIdx.x;
    const int base = idx4 * 4;
    const int o = base / NPOS;
    const int p = base - o * NPOS;
    const int b = p / NTOK;
    const int n = p - b * NTOK;

    float4 v = *(const float4*)(g_y + base);
    const float sc = g_scale[o], sh = g_shift[o];
    float r[4] = {v.x, v.y, v.z, v.w};
    #pragma unroll
    for (int i = 0; i < 4; i++) {
        float u = r[i] * sc + sh;
        r[i] = 0.5f * u * (1.f + erff(u * 0.70710678118654752f));
    }
    float4 ov = {r[0], r[1], r[2], r[3]};
    *(float4*)(out + (size_t)b * (COUT * NTOK) + (size_t)o * NTOK + n) = ov;
}

// =====================================================================
extern "C" void kernel_launch(void* const* d_in, const int* in_sizes, int n_in,
                              void* d_out, int out_size)
{
    const float* x     = (const float*)d_in[0];
    const float* w     = (const float*)d_in[1];
    const float* bias  = (const float*)d_in[2];
    const float* gamma = (const float*)d_in[3];
    const float* beta  = (const float*)d_in[4];
    float* out = (float*)d_out;

    cudaFuncSetAttribute(attn_mma_kernel, cudaFuncAttributeMaxDynamicSharedMemorySize, ATT_SMEM_BYTES);
    cudaFuncSetAttribute(conv_kernel,     cudaFuncAttributeMaxDynamicSharedMemorySize, CONV_SMEM_BYTES);

    prep_kernel<<<dim3(NPAD / 64, BATCH), 256>>>(x);
    maxn_kernel<<<BATCH, 256>>>();
    attn_mma_kernel<<<dim3(NQT, BATCH), 256, ATT_SMEM_BYTES>>>(x);
    conv_kernel<<<dim3(NPOS / 256, 3), 128, CONV_SMEM_BYTES>>>(x, w, bias);
    stats_kernel<<<COUT, 256>>>(gamma, beta);
    bngelu_kernel<<<(COUT * NPOS) / 4 / 256, 256>>>(out);
}

// round 17
// speedup vs baseline: 3.0344x; 1.2650x over previous
#include <cuda_runtime.h>
#include <cuda_bf16.h>
#include <math.h>
#include <stdint.h>

// ---------------- problem constants ----------------
#define BATCH   8
#define CH      96
#define NTOK    3136
#define NPAD    3264          // 17 * 192
#define COUT    192
#define NPOS    (BATCH * NTOK)

#define MQT     192           // queries per CTA
#define NQT     17            // 17*192 = 3264 >= 3136
#define KT      64            // keys per tile
#define NKT     49

// smem layout in bf16 elements; strides conflict-free for ldmatrix
#define QSTR 104
#define KSTR 104
#define VSTR 72
#define SQH  0
#define SQL  (MQT * QSTR)                  // 19968
#define KV0  (SQL + MQT * QSTR)            // 39936
#define KPART (KT * KSTR)                  // 6656
#define VPART (CH * VSTR)                  // 6912
#define BUFSZ (2 * KPART + 2 * VPART)      // 27136
#define SM_ELEMS (KV0 + 2 * BUFSZ)         // 94208
#define ATT_SMEM_BYTES (SM_ELEMS * 2)      // 188416

// ---------------- scratch globals ----------------
__device__ __nv_bfloat16 g_th[BATCH * NPAD * CH];   // token-major hi [b][n][c]
__device__ __nv_bfloat16 g_tl[BATCH * NPAD * CH];   // token-major lo
__device__ __nv_bfloat16 g_chm[BATCH * CH * NTOK];  // channel-major hi [b][c][n]
__device__ __nv_bfloat16 g_clm[BATCH * CH * NTOK];  // channel-major lo
__device__ float g_norm[BATCH * NPAD];
__device__ float g_maxn[BATCH];
__device__ float g_xj[BATCH * CH * NTOK];
__device__ float g_y [COUT * NPOS];
#define NCONVBLK 784
__device__ float g_p1[NCONVBLK * COUT];
__device__ float g_p2[NCONVBLK * COUT];
__device__ float g_scale[COUT];
__device__ float g_shift[COUT];

// ---------------- warp MMA / async-copy helpers (sm_80+ baseline PTX) ----
__device__ __forceinline__ uint32_t smem_u32(const void* p) {
    uint32_t a;
    asm("{ .reg .u64 t; cvta.to.shared.u64 t, %1; cvt.u32.u64 %0, t; }" : "=r"(a) : "l"(p));
    return a;
}
__device__ __forceinline__ void ldmat4(uint32_t* r, uint32_t addr) {
    asm volatile("ldmatrix.sync.aligned.m8n8.x4.shared.b16 {%0,%1,%2,%3}, [%4];"
        : "=r"(r[0]), "=r"(r[1]), "=r"(r[2]), "=r"(r[3]) : "r"(addr));
}
__device__ __forceinline__ void mma_bf16(float* d, const uint32_t* a, const uint32_t* b) {
    asm volatile("mma.sync.aligned.m16n8k16.row.col.f32.bf16.bf16.f32 "
        "{%0,%1,%2,%3}, {%4,%5,%6,%7}, {%8,%9}, {%0,%1,%2,%3};"
        : "+f"(d[0]), "+f"(d[1]), "+f"(d[2]), "+f"(d[3])
        : "r"(a[0]), "r"(a[1]), "r"(a[2]), "r"(a[3]), "r"(b[0]), "r"(b[1]));
}
#define CPA16(dst, src) asm volatile("cp.async.cg.shared.global [%0], [%1], 16;" :: "r"(dst), "l"(src) : "memory")
#define CPA_COMMIT()    asm volatile("cp.async.commit_group;" ::: "memory")
#define CPA_WAIT1()     asm volatile("cp.async.wait_group 1;" ::: "memory")
#define CPA_WAIT0()     asm volatile("cp.async.wait_group 0;" ::: "memory")

// =====================================================================
// prep: bf16 hi/lo split in token-major + channel-major layouts, norms
// grid (51, 8), 256 threads
// =====================================================================
__global__ void __launch_bounds__(256) prep_kernel(const float* __restrict__ x)
{
    __shared__ float tile[CH][65];
    const int b = blockIdx.y;
    const int n0 = blockIdx.x * 64;
    const int tid = threadIdx.x;
    const bool valid = (n0 < NTOK);
    const float* xb = x + (size_t)b * CH * NTOK;

    for (int i = tid; i < CH * 16; i += 256) {
        int c = i >> 4;
        int q4 = (i & 15) << 2;
        float4 v = make_float4(0.f, 0.f, 0.f, 0.f);
        if (valid) v = *(const float4*)(xb + (size_t)c * NTOK + n0 + q4);
        tile[c][q4+0] = v.x; tile[c][q4+1] = v.y; tile[c][q4+2] = v.z; tile[c][q4+3] = v.w;
        if (valid) {
            uint32_t h0, h1, l0, l1;
            asm("cvt.rn.bf16x2.f32 %0, %1, %2;" : "=r"(h0) : "f"(v.y), "f"(v.x));
            asm("cvt.rn.bf16x2.f32 %0, %1, %2;" : "=r"(h1) : "f"(v.w), "f"(v.z));
            float r0 = v.x - __uint_as_float(h0 << 16);
            float r1 = v.y - __uint_as_float(h0 & 0xffff0000u);
            float r2 = v.z - __uint_as_float(h1 << 16);
            float r3 = v.w - __uint_as_float(h1 & 0xffff0000u);
            asm("cvt.rn.bf16x2.f32 %0, %1, %2;" : "=r"(l0) : "f"(r1), "f"(r0));
            asm("cvt.rn.bf16x2.f32 %0, %1, %2;" : "=r"(l1) : "f"(r3), "f"(r2));
            size_t gi = ((size_t)b * CH + c) * NTOK + n0 + q4;
            *(uint2*)(g_chm + gi) = make_uint2(h0, h1);
            *(uint2*)(g_clm + gi) = make_uint2(l0, l1);
        }
    }
    __syncthreads();
    for (int i = tid; i < 64 * 12; i += 256) {
        int tt = i / 12, u = i - tt * 12;
        int c0 = u * 8;
        uint32_t h[4], lo[4];
        #pragma unroll
        for (int k = 0; k < 4; k++) {
            float a  = tile[c0 + 2*k][tt];
            float bb = tile[c0 + 2*k + 1][tt];
            asm("cvt.rn.bf16x2.f32 %0, %1, %2;" : "=r"(h[k]) : "f"(bb), "f"(a));
            float ra = a  - __uint_as_float(h[k] << 16);
            float rb = bb - __uint_as_float(h[k] & 0xffff0000u);
            asm("cvt.rn.bf16x2.f32 %0, %1, %2;" : "=r"(lo[k]) : "f"(rb), "f"(ra));
        }
        size_t gi = ((size_t)b * NPAD + n0 + tt) * CH + c0;
        *(uint4*)(g_th + gi) = make_uint4(h[0], h[1], h[2], h[3]);
        *(uint4*)(g_tl + gi) = make_uint4(lo[0], lo[1], lo[2], lo[3]);
    }
    if (tid < 64) {
        float s = 0.f;
        #pragma unroll
        for (int c = 0; c < CH; c++) { float v = tile[c][tid]; s += v * v; }
        g_norm[b * NPAD + n0 + tid] = sqrtf(s);
    }
}

__global__ void __launch_bounds__(256) maxn_kernel()
{
    const int b = blockIdx.x, tid = threadIdx.x;
    __shared__ float red[256];
    float m = 0.f;
    for (int i = tid; i < NPAD; i += 256) m = fmaxf(m, g_norm[b * NPAD + i]);
    red[tid] = m; __syncthreads();
    for (int d = 128; d > 0; d >>= 1) { if (tid < d) red[tid] = fmaxf(red[tid], red[tid + d]); __syncthreads(); }
    if (tid == 0) g_maxn[b] = red[0];
}

// =====================================================================
// attention: mma.sync bf16 split-hi/lo, static-bound softmax, O in regs
// 12 warps x M=16 rows, MQT=192, grid (17, 8) = 136 CTAs single wave
// =====================================================================
__global__ void __launch_bounds__(384)
attn_mma_kernel(const float* __restrict__ x)
{
    extern __shared__ __nv_bfloat16 sm[];
    const uint32_t sb = smem_u32(sm);
    const int tid  = threadIdx.x;
    const int wid  = tid >> 5;          // 0..11
    const int lane = tid & 31;
    const int g    = lane >> 2;
    const int tig  = lane & 3;
    const int b    = blockIdx.y;
    const int n0   = blockIdx.x * MQT;

    // ---- load Q tile (hi/lo) 192 x 96 (plain stores)
    for (int i = tid; i < MQT * 12; i += 384) {
        int r = i / 12, u = i - r * 12;
        size_t src = ((size_t)(b * NPAD + n0 + r)) * CH + u * 8;
        *(uint4*)(sm + SQH + r * QSTR + u * 8) = *(const uint4*)(g_th + src);
        *(uint4*)(sm + SQL + r * QSTR + u * 8) = *(const uint4*)(g_tl + src);
    }

    auto issue_kv = [&](int t, int d) {
        const int koff = KV0 + d * BUFSZ;
        const int voff = koff + 2 * KPART;
        const size_t ksrc = ((size_t)(b * NPAD + t * KT)) * CH;
        for (int i = tid; i < KT * 12; i += 384) {
            int r = i / 12, u = i - r * 12;
            uint32_t dst = sb + 2u * (uint32_t)(koff + r * KSTR + u * 8);
            CPA16(dst,              (const void*)(g_th + ksrc + r * CH + u * 8));
            CPA16(dst + 2u * KPART, (const void*)(g_tl + ksrc + r * CH + u * 8));
        }
        const size_t vsrc = (size_t)b * CH * NTOK + (size_t)t * KT;
        for (int i = tid; i < CH * 8; i += 384) {
            int c = i >> 3, u = i & 7;
            uint32_t dst = sb + 2u * (uint32_t)(voff + c * VSTR + u * 8);
            CPA16(dst,              (const void*)(g_chm + vsrc + (size_t)c * NTOK + u * 8));
            CPA16(dst + 2u * VPART, (const void*)(g_clm + vsrc + (size_t)c * NTOK + u * 8));
        }
    };

    issue_kv(0, 0);
    CPA_COMMIT();

    const float maxn = g_maxn[b];
    const float E0 = g_norm[b * NPAD + n0 + wid * 16 + g]     * maxn;
    const float E1 = g_norm[b * NPAD + n0 + wid * 16 + g + 8] * maxn;

    float o[12][4];
    #pragma unroll
    for (int j = 0; j < 12; j++)
        #pragma unroll
        for (int q = 0; q < 4; q++) o[j][q] = 0.f;
    float l0 = 0.f, l1 = 0.f;

    const int l16 = lane & 15;
    const int hf8 = (lane >> 4) * 8;
    const uint32_t qbase = sb + 2u * (uint32_t)(SQH + (wid * 16 + l16) * QSTR + hf8);
    const uint32_t qlo   = 2u * (uint32_t)(SQL - SQH);
    const uint32_t klo   = 2u * (uint32_t)KPART;
    const uint32_t vlo   = 2u * (uint32_t)VPART;

    for (int t = 0; t < NKT; t++) {
        if (t + 1 < NKT) {
            issue_kv(t + 1, (t + 1) & 1);
            CPA_COMMIT();
            CPA_WAIT1();
        } else {
            CPA_WAIT0();
        }
        __syncthreads();

        const int koff = KV0 + (t & 1) * BUFSZ;
        const uint32_t kbase = sb + 2u * (uint32_t)(koff + l16 * KSTR + hf8);
        const uint32_t vbase = sb + 2u * (uint32_t)(koff + 2 * KPART + l16 * VSTR + hf8);

        // ---- S = Q K^T (16 x 64 per warp), 3-term split
        float s[8][4];
        #pragma unroll
        for (int j = 0; j < 8; j++)
            #pragma unroll
            for (int q = 0; q < 4; q++) s[j][q] = 0.f;

        #pragma unroll
        for (int kb = 0; kb < 6; kb++) {
            uint32_t qh[4], ql[4];
            ldmat4(qh, qbase + kb * 32);
            ldmat4(ql, qbase + qlo + kb * 32);
            #pragma unroll
            for (int nb = 0; nb < 4; nb++) {
                uint32_t bh[4], blr[4];
                uint32_t ka = kbase + (uint32_t)(nb * 16 * KSTR * 2) + kb * 32;
                ldmat4(bh, ka);
                ldmat4(blr, ka + klo);
                uint32_t b0[2] = {bh[0], bh[2]},  b1[2] = {bh[1], bh[3]};
                uint32_t c0[2] = {blr[0], blr[2]}, c1[2] = {blr[1], blr[3]};
                mma_bf16(s[2*nb],   qh, b0);
                mma_bf16(s[2*nb+1], qh, b1);
                mma_bf16(s[2*nb],   qh, c0);
                mma_bf16(s[2*nb+1], qh, c1);
                mma_bf16(s[2*nb],   ql, b0);
                mma_bf16(s[2*nb+1], ql, b1);
            }
        }

        // ---- softmax p = exp(s - E); pack P hi/lo A-fragments in registers
        uint32_t pha[4][4], pla[4][4];
        #pragma unroll
        for (int j = 0; j < 8; j++) {
            float p0 = __expf(s[j][0] - E0);
            float p1 = __expf(s[j][1] - E0);
            float p2 = __expf(s[j][2] - E1);
            float p3 = __expf(s[j][3] - E1);
            l0 += p0 + p1; l1 += p2 + p3;
            uint32_t h01, h23, q01, q23;
            asm("cvt.rn.bf16x2.f32 %0, %1, %2;" : "=r"(h01) : "f"(p1), "f"(p0));
            asm("cvt.rn.bf16x2.f32 %0, %1, %2;" : "=r"(h23) : "f"(p3), "f"(p2));
            float r0 = p0 - __uint_as_float(h01 << 16);
            float r1 = p1 - __uint_as_float(h01 & 0xffff0000u);
            float r2 = p2 - __uint_as_float(h23 << 16);
            float r3 = p3 - __uint_as_float(h23 & 0xffff0000u);
            asm("cvt.rn.bf16x2.f32 %0, %1, %2;" : "=r"(q01) : "f"(r1), "f"(r0));
            asm("cvt.rn.bf16x2.f32 %0, %1, %2;" : "=r"(q23) : "f"(r3), "f"(r2));
            int kb = j >> 1;
            if ((j & 1) == 0) { pha[kb][0] = h01; pha[kb][1] = h23; pla[kb][0] = q01; pla[kb][1] = q23; }
            else              { pha[kb][2] = h01; pha[kb][3] = h23; pla[kb][2] = q01; pla[kb][3] = q23; }
        }

        // ---- O += P V (16 x 96 per warp), 3-term split
        #pragma unroll
        for (int kb = 0; kb < 4; kb++) {
            #pragma unroll
            for (int vb = 0; vb < 6; vb++) {
                uint32_t vh[4], vl[4];
                uint32_t va = vbase + (uint32_t)(vb * 16 * VSTR * 2) + kb * 32;
                ldmat4(vh, va);
                ldmat4(vl, va + vlo);
                uint32_t b0[2] = {vh[0], vh[2]}, b1[2] = {vh[1], vh[3]};
                uint32_t c0[2] = {vl[0], vl[2]}, c1[2] = {vl[1], vl[3]};
                mma_bf16(o[2*vb],   pha[kb], b0);
                mma_bf16(o[2*vb+1], pha[kb], b1);
                mma_bf16(o[2*vb],   pha[kb], c0);
                mma_bf16(o[2*vb+1], pha[kb], c1);
                mma_bf16(o[2*vb],   pla[kb], b0);
                mma_bf16(o[2*vb+1], pla[kb], b1);
            }
        }
        __syncthreads();
    }

    // ---- row sums across the quad
    l0 += __shfl_xor_sync(0xffffffffu, l0, 1);
    l0 += __shfl_xor_sync(0xffffffffu, l0, 2);
    l1 += __shfl_xor_sync(0xffffffffu, l1, 1);
    l1 += __shfl_xor_sync(0xffffffffu, l1, 2);
    const float i0 = 1.f / l0, i1 = 1.f / l1;

    float* stage = (float*)sm;   // 192 x 100 floats (76.8KB), reuses Q region (79.9KB)
    #pragma unroll
    for (int j = 0; j < 12; j++) {
        int c = 8 * j + 2 * tig;
        stage[(wid * 16 + g) * 100 + c]         = o[j][0] * i0;
        stage[(wid * 16 + g) * 100 + c + 1]     = o[j][1] * i0;
        stage[(wid * 16 + g + 8) * 100 + c]     = o[j][2] * i1;
        stage[(wid * 16 + g + 8) * 100 + c + 1] = o[j][3] * i1;
    }
    __syncthreads();

    const float* xb = x + (size_t)b * CH * NTOK;
    for (int i = tid; i < CH * 48; i += 384) {
        int c = i / 48, q4 = (i % 48) << 2;
        int n = n0 + q4;
        if (n < NTOK) {
            float4 xv = *(const float4*)(xb + (size_t)c * NTOK + n);
            float4 ov;
            ov.x = fmaxf(xv.x - stage[(q4 + 0) * 100 + c], 0.f);
            ov.y = fmaxf(xv.y - stage[(q4 + 1) * 100 + c], 0.f);
            ov.z = fmaxf(xv.z - stage[(q4 + 2) * 100 + c], 0.f);
            ov.w = fmaxf(xv.w - stage[(q4 + 3) * 100 + c], 0.f);
            *(float4*)(g_xj + ((size_t)b * CH + c) * NTOK + n) = ov;
        }
    }
}

// =====================================================================
// conv: grid (98, 3), 256 threads (two 128-thread halves, each its own
// chunk + cs buffer), occ 2 -> 8 warps/SMSP. WTILE=64 outs per CTA.
// =====================================================================
#define WTILE 64
#define WTSTR 68
#define CSTR  36
#define CONV_SMEM_FLOATS ((2*CH) * WTSTR + 2 * (2*CH) * CSTR)
#define CONV_SMEM_BYTES  (CONV_SMEM_FLOATS * 4)

__global__ void __launch_bounds__(256, 2)
conv_kernel(const float* __restrict__ x, const float* __restrict__ w,
            const float* __restrict__ bias)
{
    extern __shared__ float smf[];
    float* Wt = smf;                              // [192 k][68]
    const int tid  = threadIdx.x;
    const int half = tid >> 7;                    // 0..1
    const int t128 = tid & 127;
    float* cs = smf + (2*CH) * WTSTR + half * (2*CH) * CSTR;

    const int oh  = blockIdx.y;                   // 0..2
    const int obase = oh * WTILE;

    for (int i = tid; i < WTILE * (2 * CH); i += 256) {
        int o = i / (2 * CH), k = i - o * (2 * CH);
        Wt[k * WTSTR + o] = w[(obase + o) * (2 * CH) + k];
    }

    const int og = t128 >> 3;   // 0..15, owns outputs og*4..og*4+3
    const int pg = t128 & 7;    // 0..7,  owns positions pg*4..pg*4+3

    for (int c2 = 0; c2 < 4; c2++) {
        const int chunk = c2 * 2 + half;
        const int p0 = blockIdx.x * 256 + chunk * 32;
        const int b  = p0 / NTOK;
        const int n0 = p0 - b * NTOK;

        __syncthreads();
        for (int i = t128; i < (2 * CH) * 8; i += 128) {
            int k = i >> 3, u = i & 7;
            const float* src = (k < CH)
                ? (x    + ((size_t)b * CH + k) * NTOK + n0 + u * 4)
                : (g_xj + ((size_t)b * CH + (k - CH)) * NTOK + n0 + u * 4);
            *(float4*)(cs + k * CSTR + u * 4) = *(const float4*)src;
        }
        __syncthreads();

        float acc[4][4];
        #pragma unroll
        for (int j = 0; j < 4; j++)
            #pragma unroll
            for (int q = 0; q < 4; q++) acc[j][q] = 0.f;

        for (int k = 0; k < 2 * CH; k++) {
            float4 wv = *(const float4*)(Wt + k * WTSTR + og * 4);
            float4 cv = *(const float4*)(cs + k * CSTR + pg * 4);
            const float* wp = &wv.x;
            const float* cp = &cv.x;
            #pragma unroll
            for (int j = 0; j < 4; j++)
                #pragma unroll
                for (int q = 0; q < 4; q++) acc[j][q] += wp[j] * cp[q];
        }

        const int pb = blockIdx.x * 8 + chunk;
        #pragma unroll
        for (int j = 0; j < 4; j++) {
            const int o = obase + og * 4 + j;
            const float bi = bias[o];
            float a1 = 0.f, a2 = 0.f;
            #pragma unroll
            for (int q = 0; q < 4; q++) {
                float y = acc[j][q] + bi;
                g_y[(size_t)o * NPOS + p0 + pg * 4 + q] = y;
                a1 += y;
                a2 += y * y;
            }
            #pragma unroll
            for (int d = 4; d > 0; d >>= 1) {
                a1 += __shfl_down_sync(0xffffffffu, a1, d, 8);
                a2 += __shfl_down_sync(0xffffffffu, a2, d, 8);
            }
            if (pg == 0) {
                g_p1[pb * COUT + o] = a1;
                g_p2[pb * COUT + o] = a2;
            }
        }
    }
}

__global__ void __launch_bounds__(256)
stats_kernel(const float* __restrict__ gamma, const float* __restrict__ beta)
{
    const int o = blockIdx.x;
    const int tid = threadIdx.x;
    float s1 = 0.f, s2 = 0.f;
    for (int i = tid; i < NCONVBLK; i += 256) {
        s1 += g_p1[i * COUT + o];
        s2 += g_p2[i * COUT + o];
    }
    __shared__ float r1[256], r2[256];
    r1[tid] = s1; r2[tid] = s2;
    __syncthreads();
    for (int d = 128; d > 0; d >>= 1) {
        if (tid < d) { r1[tid] += r1[tid + d]; r2[tid] += r2[tid + d]; }
        __syncthreads();
    }
    if (tid == 0) {
        const float invN = 1.f / (float)NPOS;
        float mean = r1[0] * invN;
        float var  = r2[0] * invN - mean * mean;
        float rstd = rsqrtf(var + 1e-5f);
        float gg = gamma[o] * rstd;
        g_scale[o] = gg;
        g_shift[o] = beta[o] - mean * gg;
    }
}

__global__ void __launch_bounds__(256)
bngelu_kernel(float* __restrict__ out)
{
    const int idx4 = blockIdx.x * 256 + threadIdx.x;
    const int base = idx4 * 4;
    const int o = base / NPOS;
    const int p = base - o * NPOS;
    const int b = p / NTOK;
    const int n = p - b * NTOK;

    float4 v = *(const float4*)(g_y + base);
    const float sc = g_scale[o], sh = g_shift[o];
    float r[4] = {v.x, v.y, v.z, v.w};
    #pragma unroll
    for (int i = 0; i < 4; i++) {
        float u = r[i] * sc + sh;
        r[i] = 0.5f * u * (1.f + erff(u * 0.70710678118654752f));
    }
    float4 ov = {r[0], r[1], r[2], r[3]};
    *(float4*)(out + (size_t)b * (COUT * NTOK) + (size_t)o * NTOK + n) = ov;
}

// =====================================================================
extern "C" void kernel_launch(void* const* d_in, const int* in_sizes, int n_in,
                              void* d_out, int out_size)
{
    const float* x     = (const float*)d_in[0];
    const float* w     = (const float*)d_in[1];
    const float* bias  = (const float*)d_in[2];
    const float* gamma = (const float*)d_in[3];
    const float* beta  = (const float*)d_in[4];
    float* out = (float*)d_out;

    cudaFuncSetAttribute(attn_mma_kernel, cudaFuncAttributeMaxDynamicSharedMemorySize, ATT_SMEM_BYTES);
    cudaFuncSetAttribute(conv_kernel,     cudaFuncAttributeMaxDynamicSharedMemorySize, CONV_SMEM_BYTES);

    prep_kernel<<<dim3(NPAD / 64, BATCH), 256>>>(x);
    maxn_kernel<<<BATCH, 256>>>();
    attn_mma_kernel<<<dim3(NQT, BATCH), 384, ATT_SMEM_BYTES>>>(x);
    conv_kernel<<<dim3(NPOS / 256, 3), 256, CONV_SMEM_BYTES>>>(x, w, bias);
    stats_kernel<<<COUT, 256>>>(gamma, beta);
    bngelu_kernel<<<(COUT * NPOS) / 4 / 256, 256>>>(out);
}